// round 1
// baseline (speedup 1.0000x reference)
#include <cuda_runtime.h>

#define NN   4096
#define DIM  256
#define NH   4
#define HD   64
#define NE   131072
#define EDIM 64
#define LN_EPS 1e-5f

// ---------------- device scratch (no allocations allowed) ----------------
__device__ float g_Q[NH * NN * HD];                 // [h][n][d]
__device__ float g_K[NH * NN * HD];                 // [h][n][d]
__device__ float g_V[NN * DIM];                     // [n][h*64+d]
__device__ float g_S[(size_t)NN * NN * NH];         // scores [n][m][h]  (256 MB)
__device__ float g_O[NN * DIM];                     // attn output [n][256]
__device__ float g_X2[NN * DIM];                    // pre-LN

// =====================================================================
// K1: fused QKV projection.  X[4096,256] @ W[256,256] (+bias), z selects Q/K/V.
// 64x64 tile, 256 threads, 4x4 per thread.
// =====================================================================
__global__ void k_proj(const float* __restrict__ X,
                       const float* __restrict__ Wq, const float* __restrict__ bq,
                       const float* __restrict__ Wk, const float* __restrict__ bk,
                       const float* __restrict__ Wv, const float* __restrict__ bv) {
    __shared__ __align__(16) float As[16 * 68];   // [k][r]
    __shared__ __align__(16) float Bs[16 * 68];   // [k][c]
    const int t  = threadIdx.x;
    const int tx = t & 15, ty = t >> 4;
    const int c0 = blockIdx.x * 64;
    const int r0 = blockIdx.y * 64;
    const int z  = blockIdx.z;
    const float* W = (z == 0) ? Wq : (z == 1) ? Wk : Wv;
    const float* b = (z == 0) ? bq : (z == 1) ? bk : bv;

    float acc[16];
#pragma unroll
    for (int i = 0; i < 16; i++) acc[i] = 0.f;

    for (int kc = 0; kc < DIM; kc += 16) {
#pragma unroll
        for (int i = 0; i < 4; i++) {
            int idx = t + 256 * i;
            int r = idx >> 4, kk = idx & 15;
            As[kk * 68 + r] = X[(size_t)(r0 + r) * DIM + kc + kk];
        }
#pragma unroll
        for (int i = 0; i < 4; i++) {
            int idx = t + 256 * i;
            int kk = idx >> 6, c = idx & 63;
            Bs[kk * 68 + c] = W[(size_t)(kc + kk) * DIM + c0 + c];
        }
        __syncthreads();
#pragma unroll
        for (int kk = 0; kk < 16; kk++) {
            float4 a  = *reinterpret_cast<const float4*>(&As[kk * 68 + ty * 4]);
            float4 bb = *reinterpret_cast<const float4*>(&Bs[kk * 68 + tx * 4]);
            float av[4] = {a.x, a.y, a.z, a.w};
            float bv2[4] = {bb.x, bb.y, bb.z, bb.w};
#pragma unroll
            for (int i = 0; i < 4; i++)
#pragma unroll
                for (int j = 0; j < 4; j++)
                    acc[i * 4 + j] += av[i] * bv2[j];
        }
        __syncthreads();
    }

#pragma unroll
    for (int i = 0; i < 4; i++) {
        int r = r0 + ty * 4 + i;
#pragma unroll
        for (int j = 0; j < 4; j++) {
            int c = c0 + tx * 4 + j;
            float v = acc[i * 4 + j] + b[c];
            if (z == 2) {
                g_V[(size_t)r * DIM + c] = v;
            } else {
                float* dst = (z == 0) ? g_Q : g_K;
                dst[(size_t)(c >> 6) * (NN * HD) + (size_t)r * HD + (c & 63)] = v;
            }
        }
    }
}

// =====================================================================
// K3: scores[n][m][h] = 0.125 * <Q_h[n], K_h[m]> + 10 * adj[n][m]
// 64x64 (n,m) tile, all 4 heads per block, K=64 loaded whole.
// =====================================================================
__global__ void k_scores(const float* __restrict__ adj) {
    __shared__ __align__(16) float Qs[64 * 68];   // [k][n]
    __shared__ __align__(16) float Ks[64 * 68];   // [k][m]
    const int t  = threadIdx.x;
    const int tx = t & 15, ty = t >> 4;
    const int m0 = blockIdx.x * 64;
    const int n0 = blockIdx.y * 64;

    float acc[NH][16];
#pragma unroll
    for (int h = 0; h < NH; h++)
#pragma unroll
        for (int i = 0; i < 16; i++) acc[h][i] = 0.f;

#pragma unroll
    for (int h = 0; h < NH; h++) {
        const float* Qh = g_Q + (size_t)h * NN * HD;
        const float* Kh = g_K + (size_t)h * NN * HD;
#pragma unroll
        for (int i = 0; i < 4; i++) {
            int idx = t + 256 * i;           // 1024 float4 loads
            int r = idx >> 4, k4 = idx & 15;
            float4 q = *reinterpret_cast<const float4*>(&Qh[(size_t)(n0 + r) * HD + k4 * 4]);
            Qs[(k4 * 4 + 0) * 68 + r] = q.x;
            Qs[(k4 * 4 + 1) * 68 + r] = q.y;
            Qs[(k4 * 4 + 2) * 68 + r] = q.z;
            Qs[(k4 * 4 + 3) * 68 + r] = q.w;
            float4 kk = *reinterpret_cast<const float4*>(&Kh[(size_t)(m0 + r) * HD + k4 * 4]);
            Ks[(k4 * 4 + 0) * 68 + r] = kk.x;
            Ks[(k4 * 4 + 1) * 68 + r] = kk.y;
            Ks[(k4 * 4 + 2) * 68 + r] = kk.z;
            Ks[(k4 * 4 + 3) * 68 + r] = kk.w;
        }
        __syncthreads();
#pragma unroll
        for (int k = 0; k < 64; k++) {
            float4 a = *reinterpret_cast<const float4*>(&Qs[k * 68 + ty * 4]);
            float4 b = *reinterpret_cast<const float4*>(&Ks[k * 68 + tx * 4]);
            float av[4] = {a.x, a.y, a.z, a.w};
            float bv2[4] = {b.x, b.y, b.z, b.w};
#pragma unroll
            for (int i = 0; i < 4; i++)
#pragma unroll
                for (int j = 0; j < 4; j++)
                    acc[h][i * 4 + j] += av[i] * bv2[j];
        }
        __syncthreads();
    }

    const float scale = 0.125f;
#pragma unroll
    for (int i = 0; i < 4; i++) {
        int n = n0 + ty * 4 + i;
        float4 ad = *reinterpret_cast<const float4*>(&adj[(size_t)n * NN + m0 + tx * 4]);
        float adv[4] = {ad.x, ad.y, ad.z, ad.w};
#pragma unroll
        for (int j = 0; j < 4; j++) {
            int m = m0 + tx * 4 + j;
            float bias = 10.f * adv[j];
            float4 s;
            s.x = acc[0][i * 4 + j] * scale + bias;
            s.y = acc[1][i * 4 + j] * scale + bias;
            s.z = acc[2][i * 4 + j] * scale + bias;
            s.w = acc[3][i * 4 + j] * scale + bias;
            *reinterpret_cast<float4*>(&g_S[((size_t)n * NN + m) * NH]) = s;
        }
    }
}

// =====================================================================
// K2: per-edge bias  edge_attn[e,h] = ef[e,:] @ We[:,h] + be[h]
//     scatter-added into scores (duplicates accumulate via atomics).
// =====================================================================
__global__ void k_edge(const float* __restrict__ EF, const int* __restrict__ EI,
                       const float* __restrict__ We, const float* __restrict__ be) {
    __shared__ float ef[64][65];
    __shared__ float w[EDIM][NH];
    __shared__ float bsh[NH];
    const int t  = threadIdx.x;
    const int e0 = blockIdx.x * 64;
#pragma unroll
    for (int i = 0; i < 16; i++) {
        int idx = t + 256 * i;
        ef[idx >> 6][idx & 63] = EF[(size_t)e0 * EDIM + idx];
    }
    if (t < EDIM * NH) w[t >> 2][t & 3] = We[t];
    if (t < NH) bsh[t] = be[t];
    __syncthreads();

    const int el = t >> 2, h = t & 3;
    float s = bsh[h];
#pragma unroll
    for (int k = 0; k < EDIM; k++) s += ef[el][k] * w[k][h];
    const int e = e0 + el;
    const int src = EI[2 * e], tgt = EI[2 * e + 1];
    atomicAdd(&g_S[((size_t)src * NN + tgt) * NH + h], s);
}

// =====================================================================
// K4: in-place softmax over m for each (n, h). One block per n row;
// whole 64KB row held in registers (16 float4 / thread).
// =====================================================================
__device__ __forceinline__ float4 block_red4(float4 v, float4* red, bool do_max) {
    const int lane = threadIdx.x & 31, wid = threadIdx.x >> 5;
#pragma unroll
    for (int o = 16; o; o >>= 1) {
        float4 u;
        u.x = __shfl_xor_sync(0xffffffffu, v.x, o);
        u.y = __shfl_xor_sync(0xffffffffu, v.y, o);
        u.z = __shfl_xor_sync(0xffffffffu, v.z, o);
        u.w = __shfl_xor_sync(0xffffffffu, v.w, o);
        if (do_max) { v.x = fmaxf(v.x, u.x); v.y = fmaxf(v.y, u.y); v.z = fmaxf(v.z, u.z); v.w = fmaxf(v.w, u.w); }
        else        { v.x += u.x; v.y += u.y; v.z += u.z; v.w += u.w; }
    }
    if (lane == 0) red[wid] = v;
    __syncthreads();
    if (wid == 0) {
        float id = do_max ? -3.4e38f : 0.f;
        float4 u = (lane < 8) ? red[lane] : make_float4(id, id, id, id);
#pragma unroll
        for (int o = 4; o; o >>= 1) {
            float4 q;
            q.x = __shfl_xor_sync(0xffffffffu, u.x, o);
            q.y = __shfl_xor_sync(0xffffffffu, u.y, o);
            q.z = __shfl_xor_sync(0xffffffffu, u.z, o);
            q.w = __shfl_xor_sync(0xffffffffu, u.w, o);
            if (do_max) { u.x = fmaxf(u.x, q.x); u.y = fmaxf(u.y, q.y); u.z = fmaxf(u.z, q.z); u.w = fmaxf(u.w, q.w); }
            else        { u.x += q.x; u.y += q.y; u.z += q.z; u.w += q.w; }
        }
        if (lane == 0) red[0] = u;
    }
    __syncthreads();
    float4 out = red[0];
    __syncthreads();
    return out;
}

__global__ void k_softmax() {
    __shared__ float4 red[8];
    const int t = threadIdx.x;
    float4* row = reinterpret_cast<float4*>(g_S + (size_t)blockIdx.x * NN * NH);

    float4 v[16];
#pragma unroll
    for (int i = 0; i < 16; i++) v[i] = row[t + 256 * i];

    float4 mx = v[0];
#pragma unroll
    for (int i = 1; i < 16; i++) {
        mx.x = fmaxf(mx.x, v[i].x); mx.y = fmaxf(mx.y, v[i].y);
        mx.z = fmaxf(mx.z, v[i].z); mx.w = fmaxf(mx.w, v[i].w);
    }
    mx = block_red4(mx, red, true);

    float4 sm = make_float4(0.f, 0.f, 0.f, 0.f);
#pragma unroll
    for (int i = 0; i < 16; i++) {
        v[i].x = __expf(v[i].x - mx.x); sm.x += v[i].x;
        v[i].y = __expf(v[i].y - mx.y); sm.y += v[i].y;
        v[i].z = __expf(v[i].z - mx.z); sm.z += v[i].z;
        v[i].w = __expf(v[i].w - mx.w); sm.w += v[i].w;
    }
    sm = block_red4(sm, red, false);

    float4 r = make_float4(1.f / sm.x, 1.f / sm.y, 1.f / sm.z, 1.f / sm.w);
#pragma unroll
    for (int i = 0; i < 16; i++) {
        v[i].x *= r.x; v[i].y *= r.y; v[i].z *= r.z; v[i].w *= r.w;
        row[t + 256 * i] = v[i];
    }
}

// =====================================================================
// K5: out[n, h*64+d] = sum_m attn[n][m][h] * V[m][h*64+d]
// 64n x 256c tile (all heads fused -> coalesced attn reads),
// 8-way split over m with atomicAdd epilogue. g_O must be pre-zeroed.
// =====================================================================
#define KSPLIT 8
__global__ void k_zero_o() {
    g_O[blockIdx.x * blockDim.x + threadIdx.x] = 0.f;
}

__global__ void k_av() {
    __shared__ __align__(16) float As[64 * 68];   // [(m_l*4+h)][n]
    __shared__ __align__(16) float Bs[16 * 256];  // [m_l][c]
    const int t  = threadIdx.x;
    const int tx = t & 15, ty = t >> 4;
    const int n0 = blockIdx.y * 64;
    const int mbeg = blockIdx.x * (NN / KSPLIT);
    const int mend = mbeg + (NN / KSPLIT);

    float acc[NH][4][4];
#pragma unroll
    for (int h = 0; h < NH; h++)
#pragma unroll
        for (int i = 0; i < 4; i++)
#pragma unroll
            for (int j = 0; j < 4; j++) acc[h][i][j] = 0.f;

    for (int m0 = mbeg; m0 < mend; m0 += 16) {
#pragma unroll
        for (int i = 0; i < 4; i++) {
            int idx = t + 256 * i;           // 1024 float4 loads of attn
            int nl = idx >> 4, ml = idx & 15;
            float4 a = *reinterpret_cast<const float4*>(
                &g_S[((size_t)(n0 + nl) * NN + m0 + ml) * NH]);
            As[(ml * 4 + 0) * 68 + nl] = a.x;
            As[(ml * 4 + 1) * 68 + nl] = a.y;
            As[(ml * 4 + 2) * 68 + nl] = a.z;
            As[(ml * 4 + 3) * 68 + nl] = a.w;
        }
#pragma unroll
        for (int i = 0; i < 4; i++) {
            int idx = t + 256 * i;           // 1024 float4 loads of V
            int ml = idx >> 6, c4 = idx & 63;
            *reinterpret_cast<float4*>(&Bs[ml * 256 + c4 * 4]) =
                *reinterpret_cast<const float4*>(&g_V[(size_t)(m0 + ml) * DIM + c4 * 4]);
        }
        __syncthreads();
#pragma unroll
        for (int ml = 0; ml < 16; ml++) {
#pragma unroll
            for (int h = 0; h < NH; h++) {
                float4 a = *reinterpret_cast<const float4*>(&As[(ml * 4 + h) * 68 + ty * 4]);
                float4 b = *reinterpret_cast<const float4*>(&Bs[ml * 256 + h * 64 + tx * 4]);
                float av[4] = {a.x, a.y, a.z, a.w};
                float bv2[4] = {b.x, b.y, b.z, b.w};
#pragma unroll
                for (int i = 0; i < 4; i++)
#pragma unroll
                    for (int j = 0; j < 4; j++)
                        acc[h][i][j] += av[i] * bv2[j];
            }
        }
        __syncthreads();
    }

#pragma unroll
    for (int h = 0; h < NH; h++)
#pragma unroll
        for (int i = 0; i < 4; i++)
#pragma unroll
            for (int j = 0; j < 4; j++)
                atomicAdd(&g_O[(size_t)(n0 + ty * 4 + i) * DIM + h * 64 + tx * 4 + j],
                          acc[h][i][j]);
}

// =====================================================================
// K6a: g_X2 = g_O @ Wo + bo + X   (64x64 tile GEMM, K=256)
// =====================================================================
__global__ void k_oproj(const float* __restrict__ Wo, const float* __restrict__ bo,
                        const float* __restrict__ X) {
    __shared__ __align__(16) float As[16 * 68];
    __shared__ __align__(16) float Bs[16 * 68];
    const int t  = threadIdx.x;
    const int tx = t & 15, ty = t >> 4;
    const int c0 = blockIdx.x * 64;
    const int r0 = blockIdx.y * 64;

    float acc[16];
#pragma unroll
    for (int i = 0; i < 16; i++) acc[i] = 0.f;

    for (int kc = 0; kc < DIM; kc += 16) {
#pragma unroll
        for (int i = 0; i < 4; i++) {
            int idx = t + 256 * i;
            int r = idx >> 4, kk = idx & 15;
            As[kk * 68 + r] = g_O[(size_t)(r0 + r) * DIM + kc + kk];
        }
#pragma unroll
        for (int i = 0; i < 4; i++) {
            int idx = t + 256 * i;
            int kk = idx >> 6, c = idx & 63;
            Bs[kk * 68 + c] = Wo[(size_t)(kc + kk) * DIM + c0 + c];
        }
        __syncthreads();
#pragma unroll
        for (int kk = 0; kk < 16; kk++) {
            float4 a  = *reinterpret_cast<const float4*>(&As[kk * 68 + ty * 4]);
            float4 bb = *reinterpret_cast<const float4*>(&Bs[kk * 68 + tx * 4]);
            float av[4] = {a.x, a.y, a.z, a.w};
            float bv2[4] = {bb.x, bb.y, bb.z, bb.w};
#pragma unroll
            for (int i = 0; i < 4; i++)
#pragma unroll
                for (int j = 0; j < 4; j++)
                    acc[i * 4 + j] += av[i] * bv2[j];
        }
        __syncthreads();
    }

#pragma unroll
    for (int i = 0; i < 4; i++) {
        int r = r0 + ty * 4 + i;
#pragma unroll
        for (int j = 0; j < 4; j++) {
            int c = c0 + tx * 4 + j;
            g_X2[(size_t)r * DIM + c] = acc[i * 4 + j] + bo[c] + X[(size_t)r * DIM + c];
        }
    }
}

// =====================================================================
// K6b: LayerNorm per row (exactly matches reference: mean, then mean((x-mu)^2))
// =====================================================================
__device__ __forceinline__ float block_sum(float v, float* red) {
    const int lane = threadIdx.x & 31, wid = threadIdx.x >> 5;
#pragma unroll
    for (int o = 16; o; o >>= 1) v += __shfl_xor_sync(0xffffffffu, v, o);
    if (lane == 0) red[wid] = v;
    __syncthreads();
    if (wid == 0) {
        float s = (lane < 8) ? red[lane] : 0.f;
#pragma unroll
        for (int o = 4; o; o >>= 1) s += __shfl_xor_sync(0xffffffffu, s, o);
        if (lane == 0) red[0] = s;
    }
    __syncthreads();
    float r = red[0];
    __syncthreads();
    return r;
}

__global__ void k_ln(const float* __restrict__ gamma, const float* __restrict__ beta,
                     float* __restrict__ out) {
    __shared__ float red[8];
    const int t = threadIdx.x;
    const int n = blockIdx.x;
    float x = g_X2[(size_t)n * DIM + t];
    float mu = block_sum(x, red) * (1.f / DIM);
    float d = x - mu;
    float var = block_sum(d * d, red) * (1.f / DIM);
    out[(size_t)n * DIM + t] = gamma[t] * d * rsqrtf(var + LN_EPS) + beta[t];
}

// =====================================================================
extern "C" void kernel_launch(void* const* d_in, const int* in_sizes, int n_in,
                              void* d_out, int out_size) {
    const float* X    = (const float*)d_in[0];
    const float* adj  = (const float*)d_in[1];
    const float* EF   = (const float*)d_in[2];
    const int*   EI   = (const int*)  d_in[3];
    const float* Wq   = (const float*)d_in[4];
    const float* bq   = (const float*)d_in[5];
    const float* Wk   = (const float*)d_in[6];
    const float* bk   = (const float*)d_in[7];
    const float* Wv   = (const float*)d_in[8];
    const float* bv   = (const float*)d_in[9];
    const float* We   = (const float*)d_in[10];
    const float* be   = (const float*)d_in[11];
    const float* Wo   = (const float*)d_in[12];
    const float* bo   = (const float*)d_in[13];
    const float* gam  = (const float*)d_in[14];
    const float* bet  = (const float*)d_in[15];
    float* out = (float*)d_out;

    k_proj   <<<dim3(4, 64, 3), 256>>>(X, Wq, bq, Wk, bk, Wv, bv);
    k_scores <<<dim3(64, 64),   256>>>(adj);
    k_edge   <<<NE / 64,        256>>>(EF, EI, We, be);
    k_softmax<<<NN,             256>>>();
    k_zero_o <<<(NN * DIM) / 256, 256>>>();
    k_av     <<<dim3(KSPLIT, 64), 256>>>();
    k_oproj  <<<dim3(4, 64),    256>>>(Wo, bo, X);
    k_ln     <<<NN,             256>>>(gam, bet, out);
}

// round 3
// speedup vs baseline: 1.8857x; 1.8857x over previous
#include <cuda_runtime.h>
#include <cuda_bf16.h>
#include <cstdint>

#define NN   4096
#define DIM  256
#define NH   4
#define HD   64
#define NE   131072
#define EDIM 64
#define LN_EPS 1e-5f

// ---------------- device scratch ----------------
__device__ float g_S[(size_t)NH * NN * NN];         // scores [h][n][m]  (256 MB)
__device__ __nv_bfloat16 g_Qh[NH * NN * HD], g_Ql[NH * NN * HD];  // [h][n][d]
__device__ __nv_bfloat16 g_Kh[NH * NN * HD], g_Kl[NH * NN * HD];  // [h][n][d]
__device__ __nv_bfloat16 g_Vh[NH * HD * NN], g_Vl[NH * HD * NN];  // [h][d][m]
__device__ float g_mx[NH * NN], g_ri[NH * NN];
__device__ float g_O[NN * DIM];
__device__ float g_X2[NN * DIM];

// ---------------- helpers ----------------
__device__ __forceinline__ uint32_t smem_to_u32(const void* p) {
    uint32_t a;
    asm("{ .reg .u64 t; cvta.to.shared.u64 t, %1; cvt.u32.u64 %0, t; }" : "=r"(a) : "l"(p));
    return a;
}
#define SW128(b) ((b) ^ (((b) >> 3) & 0x70))

__device__ __forceinline__ void ldsm4(uint32_t r[4], uint32_t addr) {
    asm volatile("ldmatrix.sync.aligned.m8n8.x4.shared.b16 {%0,%1,%2,%3}, [%4];"
        : "=r"(r[0]), "=r"(r[1]), "=r"(r[2]), "=r"(r[3]) : "r"(addr));
}
__device__ __forceinline__ void mma_bf16(float c[4], const uint32_t a[4],
                                         uint32_t b0, uint32_t b1) {
    asm volatile("mma.sync.aligned.m16n8k16.row.col.f32.bf16.bf16.f32 "
        "{%0,%1,%2,%3}, {%4,%5,%6,%7}, {%8,%9}, {%0,%1,%2,%3};"
        : "+f"(c[0]), "+f"(c[1]), "+f"(c[2]), "+f"(c[3])
        : "r"(a[0]), "r"(a[1]), "r"(a[2]), "r"(a[3]), "r"(b0), "r"(b1));
}
__device__ __forceinline__ uint32_t pack_bf16f(float a, float b) {
    __nv_bfloat162 t;
    t.x = __float2bfloat16(a);
    t.y = __float2bfloat16(b);
    return *reinterpret_cast<uint32_t*>(&t);
}

// =====================================================================
// K1: fused QKV projection -> bf16 hi/lo splits.
// =====================================================================
__global__ void k_proj(const float* __restrict__ X,
                       const float* __restrict__ Wq, const float* __restrict__ bq,
                       const float* __restrict__ Wk, const float* __restrict__ bk,
                       const float* __restrict__ Wv, const float* __restrict__ bv) {
    __shared__ __align__(16) float As[16 * 68];
    __shared__ __align__(16) float Bs[16 * 68];
    const int t  = threadIdx.x;
    const int tx = t & 15, ty = t >> 4;
    const int c0 = blockIdx.x * 64;
    const int r0 = blockIdx.y * 64;
    const int z  = blockIdx.z;
    const float* W = (z == 0) ? Wq : (z == 1) ? Wk : Wv;
    const float* b = (z == 0) ? bq : (z == 1) ? bk : bv;

    float acc[16];
#pragma unroll
    for (int i = 0; i < 16; i++) acc[i] = 0.f;

    for (int kc = 0; kc < DIM; kc += 16) {
#pragma unroll
        for (int i = 0; i < 4; i++) {
            int idx = t + 256 * i;
            int r = idx >> 4, kk = idx & 15;
            As[kk * 68 + r] = X[(size_t)(r0 + r) * DIM + kc + kk];
        }
#pragma unroll
        for (int i = 0; i < 4; i++) {
            int idx = t + 256 * i;
            int kk = idx >> 6, c = idx & 63;
            Bs[kk * 68 + c] = W[(size_t)(kc + kk) * DIM + c0 + c];
        }
        __syncthreads();
#pragma unroll
        for (int kk = 0; kk < 16; kk++) {
            float4 a  = *reinterpret_cast<const float4*>(&As[kk * 68 + ty * 4]);
            float4 bb = *reinterpret_cast<const float4*>(&Bs[kk * 68 + tx * 4]);
            float av[4] = {a.x, a.y, a.z, a.w};
            float bv2[4] = {bb.x, bb.y, bb.z, bb.w};
#pragma unroll
            for (int i = 0; i < 4; i++)
#pragma unroll
                for (int j = 0; j < 4; j++)
                    acc[i * 4 + j] += av[i] * bv2[j];
        }
        __syncthreads();
    }

#pragma unroll
    for (int i = 0; i < 4; i++) {
        int r = r0 + ty * 4 + i;
#pragma unroll
        for (int j = 0; j < 4; j++) {
            int c = c0 + tx * 4 + j;
            float v = acc[i * 4 + j] + b[c];
            int h = c >> 6, d = c & 63;
            __nv_bfloat16 hi = __float2bfloat16(v);
            __nv_bfloat16 lo = __float2bfloat16(v - __bfloat162float(hi));
            if (z == 0) {
                size_t idx = ((size_t)h * NN + r) * HD + d;
                g_Qh[idx] = hi; g_Ql[idx] = lo;
            } else if (z == 1) {
                size_t idx = ((size_t)h * NN + r) * HD + d;
                g_Kh[idx] = hi; g_Kl[idx] = lo;
            } else {
                size_t idx = ((size_t)h * HD + d) * NN + r;   // [h][d][m]
                g_Vh[idx] = hi; g_Vl[idx] = lo;
            }
        }
    }
}

// =====================================================================
// K2: scores via mma.sync bf16 hi/lo. S[h][n][m] = 0.125*<Q,K> + 10*adj.
// CTA: 128n x 128m, loops over all 4 heads; adj tile staged once in smem.
// Dyn smem: QH 16K | QL 16K | KH 16K | KL 16K | adj 64K = 128K.
// =====================================================================
#define SC_SMEM (65536 + 65536)

__global__ void __launch_bounds__(256, 1) k_scores_mma(const float* __restrict__ adj) {
    extern __shared__ char smem[];
    const int t = threadIdx.x, lane = t & 31, wid = t >> 5;
    const int m0 = blockIdx.x * 128, n0 = blockIdx.y * 128;
    const int wn = wid >> 1, wm = wid & 1;
    const uint32_t sQH = smem_to_u32(smem);
    const uint32_t sQL = sQH + 16384, sKH = sQH + 32768, sKL = sQH + 49152;
    float* adjs = (float*)(smem + 65536);

#pragma unroll
    for (int i = 0; i < 16; i++) {
        int e = t + 256 * i;
        int r = e >> 5, c = e & 31;
        *(float4*)(adjs + r * 128 + c * 4) =
            *(const float4*)(adj + (size_t)(n0 + r) * NN + m0 + c * 4);
    }

    const uint32_t aRow = wn * 32 + (lane & 15);
    const uint32_t bRow = wm * 64 + (lane & 15);
    const uint32_t cOff = (lane >> 4) * 16;
    const int g = lane >> 2, tg = lane & 3;

    for (int h = 0; h < NH; h++) {
        __syncthreads();
        {
            const uint4* q_h = (const uint4*)(g_Qh + ((size_t)h * NN + n0) * HD);
            const uint4* q_l = (const uint4*)(g_Ql + ((size_t)h * NN + n0) * HD);
            const uint4* k_h = (const uint4*)(g_Kh + ((size_t)h * NN + m0) * HD);
            const uint4* k_l = (const uint4*)(g_Kl + ((size_t)h * NN + m0) * HD);
#pragma unroll
            for (int i = 0; i < 4; i++) {
                int e = t + 256 * i;
                uint32_t sw = SW128((uint32_t)e * 16);
                *(uint4*)(smem + sw)         = q_h[e];
                *(uint4*)(smem + 16384 + sw) = q_l[e];
                *(uint4*)(smem + 32768 + sw) = k_h[e];
                *(uint4*)(smem + 49152 + sw) = k_l[e];
            }
        }
        __syncthreads();

        float c[2][8][4];
#pragma unroll
        for (int fn = 0; fn < 2; fn++)
#pragma unroll
            for (int fm = 0; fm < 8; fm++)
#pragma unroll
                for (int k = 0; k < 4; k++) c[fn][fm][k] = 0.f;

#pragma unroll
        for (int ks = 0; ks < 4; ks++) {
            uint32_t aH[2][4], aL[2][4], bH[4][4], bL[4][4];
#pragma unroll
            for (int fn = 0; fn < 2; fn++) {
                uint32_t byte = (aRow + fn * 16) * 128 + ks * 32 + cOff;
                ldsm4(aH[fn], sQH + SW128(byte));
                ldsm4(aL[fn], sQL + SW128(byte));
            }
#pragma unroll
            for (int fg = 0; fg < 4; fg++) {
                uint32_t byte = (bRow + fg * 16) * 128 + ks * 32 + cOff;
                ldsm4(bH[fg], sKH + SW128(byte));
                ldsm4(bL[fg], sKL + SW128(byte));
            }
#pragma unroll
            for (int fn = 0; fn < 2; fn++)
#pragma unroll
                for (int fg = 0; fg < 4; fg++) {
                    mma_bf16(c[fn][2*fg],   aH[fn], bH[fg][0], bH[fg][2]);
                    mma_bf16(c[fn][2*fg],   aH[fn], bL[fg][0], bL[fg][2]);
                    mma_bf16(c[fn][2*fg],   aL[fn], bH[fg][0], bH[fg][2]);
                    mma_bf16(c[fn][2*fg+1], aH[fn], bH[fg][1], bH[fg][3]);
                    mma_bf16(c[fn][2*fg+1], aH[fn], bL[fg][1], bL[fg][3]);
                    mma_bf16(c[fn][2*fg+1], aL[fn], bH[fg][1], bH[fg][3]);
                }
        }

        float* Sout = g_S + ((size_t)h * NN + n0) * NN + m0;
#pragma unroll
        for (int fn = 0; fn < 2; fn++) {
            int r0 = wn * 32 + fn * 16 + g;
#pragma unroll
            for (int fm = 0; fm < 8; fm++) {
                int col = wm * 64 + fm * 8 + tg * 2;
                float2 o0, o1;
                o0.x = c[fn][fm][0] * 0.125f + 10.f * adjs[r0 * 128 + col];
                o0.y = c[fn][fm][1] * 0.125f + 10.f * adjs[r0 * 128 + col + 1];
                o1.x = c[fn][fm][2] * 0.125f + 10.f * adjs[(r0 + 8) * 128 + col];
                o1.y = c[fn][fm][3] * 0.125f + 10.f * adjs[(r0 + 8) * 128 + col + 1];
                *(float2*)(Sout + (size_t)r0 * NN + col) = o0;
                *(float2*)(Sout + (size_t)(r0 + 8) * NN + col) = o1;
            }
        }
    }
}

// =====================================================================
// K3: per-edge bias scatter-add into S[h][src][tgt]
// =====================================================================
__global__ void k_edge(const float* __restrict__ EF, const int* __restrict__ EI,
                       const float* __restrict__ We, const float* __restrict__ be) {
    __shared__ float ef[64][65];
    __shared__ float w[EDIM][NH];
    __shared__ float bsh[NH];
    const int t  = threadIdx.x;
    const int e0 = blockIdx.x * 64;
#pragma unroll
    for (int i = 0; i < 16; i++) {
        int idx = t + 256 * i;
        ef[idx >> 6][idx & 63] = EF[(size_t)e0 * EDIM + idx];
    }
    if (t < EDIM * NH) w[t >> 2][t & 3] = We[t];
    if (t < NH) bsh[t] = be[t];
    __syncthreads();

    const int el = t >> 2, h = t & 3;
    float s = bsh[h];
#pragma unroll
    for (int k = 0; k < EDIM; k++) s += ef[el][k] * w[k][h];
    const int e = e0 + el;
    const int src = EI[2 * e], tgt = EI[2 * e + 1];
    atomicAdd(&g_S[(size_t)h * NN * NN + (size_t)src * NN + tgt], s);
}

// =====================================================================
// K4: row stats (max, 1/sum(exp)) per (h, n)
// =====================================================================
__device__ __forceinline__ float blk_red(float v, float* red, bool do_max) {
    const int lane = threadIdx.x & 31, wid = threadIdx.x >> 5;
#pragma unroll
    for (int o = 16; o; o >>= 1) {
        float u = __shfl_xor_sync(0xffffffffu, v, o);
        v = do_max ? fmaxf(v, u) : (v + u);
    }
    if (lane == 0) red[wid] = v;
    __syncthreads();
    if (wid == 0) {
        float s = (lane < 8) ? red[lane] : (do_max ? -3.4e38f : 0.f);
#pragma unroll
        for (int o = 4; o; o >>= 1) {
            float u = __shfl_xor_sync(0xffffffffu, s, o);
            s = do_max ? fmaxf(s, u) : (s + u);
        }
        if (lane == 0) red[0] = s;
    }
    __syncthreads();
    float r = red[0];
    __syncthreads();
    return r;
}

__global__ void k_stats() {
    __shared__ float red[8];
    const int t = threadIdx.x, n = blockIdx.x, h = blockIdx.y;
    const float4* row = (const float4*)(g_S + ((size_t)h * NN + n) * NN);
    float4 v[4];
#pragma unroll
    for (int i = 0; i < 4; i++) v[i] = row[t + 256 * i];
    float mx = -3.4e38f;
#pragma unroll
    for (int i = 0; i < 4; i++)
        mx = fmaxf(mx, fmaxf(fmaxf(v[i].x, v[i].y), fmaxf(v[i].z, v[i].w)));
    mx = blk_red(mx, red, true);
    float s = 0.f;
#pragma unroll
    for (int i = 0; i < 4; i++)
        s += __expf(v[i].x - mx) + __expf(v[i].y - mx) +
             __expf(v[i].z - mx) + __expf(v[i].w - mx);
    s = blk_red(s, red, false);
    if (t == 0) {
        g_mx[h * NN + n] = mx;
        g_ri[h * NN + n] = 1.f / s;
    }
}

// =====================================================================
// K5: attn@V via mma.sync, softmax fused (P = exp(S - mx) built on the fly,
// hi/lo split). CTA: 128n x 64d per head, m-loop in 64 chunks, reg-prefetched.
// Dyn smem: PH 16K | PL 16K | VH 8K | VL 8K | mx 512 | ri 512 = 50176.
// =====================================================================
#define AV_SMEM 50176

__global__ void __launch_bounds__(256, 1) k_av_mma() {
    extern __shared__ char smem[];
    const int t = threadIdx.x, lane = t & 31, wid = t >> 5;
    const int n0 = blockIdx.x * 128, h = blockIdx.y;
    const uint32_t sPH = smem_to_u32(smem);
    const uint32_t sPL = sPH + 16384, sVH = sPH + 32768, sVL = sPH + 40960;
    float* smx = (float*)(smem + 49152);
    float* sri = (float*)(smem + 49664);

    if (t < 128) {
        smx[t] = g_mx[h * NN + n0 + t];
        sri[t] = g_ri[h * NN + n0 + t];
    }
    __syncthreads();

    const float* Sbase = g_S + ((size_t)h * NN + n0) * NN;
    const __nv_bfloat16* Vh = g_Vh + (size_t)h * HD * NN;
    const __nv_bfloat16* Vl = g_Vl + (size_t)h * HD * NN;

    const int pRow = t >> 4, pC = t & 15;      // S staging: rows pRow+16i, float4 col pC
    const int vRow = t >> 3, vC = t & 7;       // V staging: rows vRow+32i, uint4 col vC

    float4 sr[8];
    uint4 vhr[2], vlr[2];
#pragma unroll
    for (int i = 0; i < 8; i++)
        sr[i] = *(const float4*)(Sbase + (size_t)(pRow + 16 * i) * NN + pC * 4);
#pragma unroll
    for (int i = 0; i < 2; i++) {
        vhr[i] = *(const uint4*)(Vh + (size_t)(vRow + 32 * i) * NN + vC * 8);
        vlr[i] = *(const uint4*)(Vl + (size_t)(vRow + 32 * i) * NN + vC * 8);
    }

    float c[8][4];
#pragma unroll
    for (int fd = 0; fd < 8; fd++)
#pragma unroll
        for (int k = 0; k < 4; k++) c[fd][k] = 0.f;

    const uint32_t aRow = wid * 16 + (lane & 15);
    const uint32_t cOff = (lane >> 4) * 16;

    for (int j = 0; j < 64; j++) {
        // convert prefetched S -> exp -> hi/lo bf16 -> smem
#pragma unroll
        for (int i = 0; i < 8; i++) {
            int row = pRow + 16 * i;
            float mxr = smx[row];
            float p0 = __expf(sr[i].x - mxr), p1 = __expf(sr[i].y - mxr);
            float p2 = __expf(sr[i].z - mxr), p3 = __expf(sr[i].w - mxr);
            __nv_bfloat16 h0 = __float2bfloat16(p0), h1 = __float2bfloat16(p1);
            __nv_bfloat16 h2 = __float2bfloat16(p2), h3 = __float2bfloat16(p3);
            uint2 hv, lv;
            { __nv_bfloat162 u; u.x = h0; u.y = h1; hv.x = *(uint32_t*)&u;
              u.x = h2; u.y = h3; hv.y = *(uint32_t*)&u; }
            lv.x = pack_bf16f(p0 - __bfloat162float(h0), p1 - __bfloat162float(h1));
            lv.y = pack_bf16f(p2 - __bfloat162float(h2), p3 - __bfloat162float(h3));
            uint32_t sw = SW128((uint32_t)(row * 128 + pC * 8));
            *(uint2*)(smem + sw)         = hv;
            *(uint2*)(smem + 16384 + sw) = lv;
        }
#pragma unroll
        for (int i = 0; i < 2; i++) {
            int e = t + 256 * i;
            uint32_t sw = SW128((uint32_t)e * 16);
            *(uint4*)(smem + 32768 + sw) = vhr[i];
            *(uint4*)(smem + 40960 + sw) = vlr[i];
        }
        __syncthreads();

        if (j < 63) {                           // prefetch next chunk
            const int m1 = (j + 1) * 64;
#pragma unroll
            for (int i = 0; i < 8; i++)
                sr[i] = *(const float4*)(Sbase + (size_t)(pRow + 16 * i) * NN + m1 + pC * 4);
#pragma unroll
            for (int i = 0; i < 2; i++) {
                vhr[i] = *(const uint4*)(Vh + (size_t)(vRow + 32 * i) * NN + m1 + vC * 8);
                vlr[i] = *(const uint4*)(Vl + (size_t)(vRow + 32 * i) * NN + m1 + vC * 8);
            }
        }

#pragma unroll
        for (int ks = 0; ks < 4; ks++) {
            uint32_t aH[4], aL[4], bH[4][4], bL[4][4];
            uint32_t byte = aRow * 128 + ks * 32 + cOff;
            ldsm4(aH, sPH + SW128(byte));
            ldsm4(aL, sPL + SW128(byte));
#pragma unroll
            for (int fg = 0; fg < 4; fg++) {
                uint32_t bb = (fg * 16 + (lane & 15)) * 128 + ks * 32 + cOff;
                ldsm4(bH[fg], sVH + SW128(bb));
                ldsm4(bL[fg], sVL + SW128(bb));
            }
#pragma unroll
            for (int fg = 0; fg < 4; fg++) {
                mma_bf16(c[2*fg],   aH, bH[fg][0], bH[fg][2]);
                mma_bf16(c[2*fg],   aH, bL[fg][0], bL[fg][2]);
                mma_bf16(c[2*fg],   aL, bH[fg][0], bH[fg][2]);
                mma_bf16(c[2*fg+1], aH, bH[fg][1], bH[fg][3]);
                mma_bf16(c[2*fg+1], aH, bL[fg][1], bL[fg][3]);
                mma_bf16(c[2*fg+1], aL, bH[fg][1], bH[fg][3]);
            }
        }
        __syncthreads();
    }

    const int g = lane >> 2, tg = lane & 3;
    const int r0 = wid * 16 + g;
    const float ri0 = sri[r0], ri8 = sri[r0 + 8];
    float* dst0 = g_O + (size_t)(n0 + r0) * DIM + h * HD;
    float* dst8 = g_O + (size_t)(n0 + r0 + 8) * DIM + h * HD;
#pragma unroll
    for (int fd = 0; fd < 8; fd++) {
        int col = fd * 8 + tg * 2;
        float2 o0 = { c[fd][0] * ri0, c[fd][1] * ri0 };
        float2 o1 = { c[fd][2] * ri8, c[fd][3] * ri8 };
        *(float2*)(dst0 + col) = o0;
        *(float2*)(dst8 + col) = o1;
    }
}

// =====================================================================
// K6a: g_X2 = g_O @ Wo + bo + X
// =====================================================================
__global__ void k_oproj(const float* __restrict__ Wo, const float* __restrict__ bo,
                        const float* __restrict__ X) {
    __shared__ __align__(16) float As[16 * 68];
    __shared__ __align__(16) float Bs[16 * 68];
    const int t  = threadIdx.x;
    const int tx = t & 15, ty = t >> 4;
    const int c0 = blockIdx.x * 64;
    const int r0 = blockIdx.y * 64;

    float acc[16];
#pragma unroll
    for (int i = 0; i < 16; i++) acc[i] = 0.f;

    for (int kc = 0; kc < DIM; kc += 16) {
#pragma unroll
        for (int i = 0; i < 4; i++) {
            int idx = t + 256 * i;
            int r = idx >> 4, kk = idx & 15;
            As[kk * 68 + r] = g_O[(size_t)(r0 + r) * DIM + kc + kk];
        }
#pragma unroll
        for (int i = 0; i < 4; i++) {
            int idx = t + 256 * i;
            int kk = idx >> 6, c = idx & 63;
            Bs[kk * 68 + c] = Wo[(size_t)(kc + kk) * DIM + c0 + c];
        }
        __syncthreads();
#pragma unroll
        for (int kk = 0; kk < 16; kk++) {
            float4 a  = *reinterpret_cast<const float4*>(&As[kk * 68 + ty * 4]);
            float4 bb = *reinterpret_cast<const float4*>(&Bs[kk * 68 + tx * 4]);
            float av[4] = {a.x, a.y, a.z, a.w};
            float bv2[4] = {bb.x, bb.y, bb.z, bb.w};
#pragma unroll
            for (int i = 0; i < 4; i++)
#pragma unroll
                for (int j = 0; j < 4; j++)
                    acc[i * 4 + j] += av[i] * bv2[j];
        }
        __syncthreads();
    }

#pragma unroll
    for (int i = 0; i < 4; i++) {
        int r = r0 + ty * 4 + i;
#pragma unroll
        for (int j = 0; j < 4; j++) {
            int c = c0 + tx * 4 + j;
            g_X2[(size_t)r * DIM + c] = acc[i * 4 + j] + bo[c] + X[(size_t)r * DIM + c];
        }
    }
}

// =====================================================================
// K6b: LayerNorm
// =====================================================================
__global__ void k_ln(const float* __restrict__ gamma, const float* __restrict__ beta,
                     float* __restrict__ out) {
    __shared__ float red[8];
    const int t = threadIdx.x;
    const int n = blockIdx.x;
    float x = g_X2[(size_t)n * DIM + t];
    float mu = blk_red(x, red, false) * (1.f / DIM);
    float d = x - mu;
    float var = blk_red(d * d, red, false) * (1.f / DIM);
    out[(size_t)n * DIM + t] = gamma[t] * d * rsqrtf(var + LN_EPS) + beta[t];
}

// =====================================================================
extern "C" void kernel_launch(void* const* d_in, const int* in_sizes, int n_in,
                              void* d_out, int out_size) {
    const float* X    = (const float*)d_in[0];
    const float* adj  = (const float*)d_in[1];
    const float* EF   = (const float*)d_in[2];
    const int*   EI   = (const int*)  d_in[3];
    const float* Wq   = (const float*)d_in[4];
    const float* bq   = (const float*)d_in[5];
    const float* Wk   = (const float*)d_in[6];
    const float* bk   = (const float*)d_in[7];
    const float* Wv   = (const float*)d_in[8];
    const float* bv   = (const float*)d_in[9];
    const float* We   = (const float*)d_in[10];
    const float* be   = (const float*)d_in[11];
    const float* Wo   = (const float*)d_in[12];
    const float* bo   = (const float*)d_in[13];
    const float* gam  = (const float*)d_in[14];
    const float* bet  = (const float*)d_in[15];
    float* out = (float*)d_out;

    cudaFuncSetAttribute(k_scores_mma, cudaFuncAttributeMaxDynamicSharedMemorySize, SC_SMEM);
    cudaFuncSetAttribute(k_av_mma,     cudaFuncAttributeMaxDynamicSharedMemorySize, AV_SMEM);

    k_proj      <<<dim3(4, 64, 3), 256>>>(X, Wq, bq, Wk, bk, Wv, bv);
    k_scores_mma<<<dim3(32, 32), 256, SC_SMEM>>>(adj);
    k_edge      <<<NE / 64, 256>>>(EF, EI, We, be);
    k_stats     <<<dim3(NN, NH), 256>>>();
    k_av_mma    <<<dim3(32, NH), 256, AV_SMEM>>>();
    k_oproj     <<<dim3(4, 64), 256>>>(Wo, bo, X);
    k_ln        <<<NN, 256>>>(gam, bet, out);
}

// round 4
// speedup vs baseline: 1.9236x; 1.0201x over previous
#include <cuda_runtime.h>
#include <cuda_bf16.h>
#include <cstdint>

#define NN   4096
#define DIM  256
#define NH   4
#define HD   64
#define NE   131072
#define EDIM 64
#define LN_EPS 1e-5f

// ---------------- device scratch ----------------
__device__ __nv_bfloat16 g_Qh[NH * NN * HD], g_Ql[NH * NN * HD];  // [h][n][d]
__device__ __nv_bfloat16 g_Kh[NH * NN * HD], g_Kl[NH * NN * HD];  // [h][m][d]
__device__ __nv_bfloat16 g_Vh[NH * HD * NN], g_Vl[NH * HD * NN];  // [h][d][m]
__device__ float g_EA[(size_t)NE * NH];     // per-edge attn bias [e][h]
__device__ int   g_bcnt[2048];              // bucket histogram (nb*64 + mchunk)
__device__ int   g_boff[2049];              // exclusive offsets
__device__ int   g_bcur[2048];              // scatter cursors
__device__ int   g_blist[NE];               // bucketed edge ids
__device__ float g_O[NN * DIM];
__device__ float g_X2[NN * DIM];

// ---------------- helpers ----------------
__device__ __forceinline__ uint32_t smem_to_u32(const void* p) {
    uint32_t a;
    asm("{ .reg .u64 t; cvta.to.shared.u64 t, %1; cvt.u32.u64 %0, t; }" : "=r"(a) : "l"(p));
    return a;
}
#define SW128(b) ((b) ^ (((b) >> 3) & 0x70))

__device__ __forceinline__ void ldsm4(uint32_t r[4], uint32_t addr) {
    asm volatile("ldmatrix.sync.aligned.m8n8.x4.shared.b16 {%0,%1,%2,%3}, [%4];"
        : "=r"(r[0]), "=r"(r[1]), "=r"(r[2]), "=r"(r[3]) : "r"(addr));
}
__device__ __forceinline__ void mma_bf16(float c[4], const uint32_t a[4],
                                         uint32_t b0, uint32_t b1) {
    asm volatile("mma.sync.aligned.m16n8k16.row.col.f32.bf16.bf16.f32 "
        "{%0,%1,%2,%3}, {%4,%5,%6,%7}, {%8,%9}, {%0,%1,%2,%3};"
        : "+f"(c[0]), "+f"(c[1]), "+f"(c[2]), "+f"(c[3])
        : "r"(a[0]), "r"(a[1]), "r"(a[2]), "r"(a[3]), "r"(b0), "r"(b1));
}
__device__ __forceinline__ uint32_t pack_bf16f(float a, float b) {
    __nv_bfloat162 t;
    t.x = __float2bfloat16(a);
    t.y = __float2bfloat16(b);
    return *reinterpret_cast<uint32_t*>(&t);
}

// =====================================================================
// K1: fused QKV projection -> bf16 hi/lo splits.
// =====================================================================
__global__ void k_proj(const float* __restrict__ X,
                       const float* __restrict__ Wq, const float* __restrict__ bq,
                       const float* __restrict__ Wk, const float* __restrict__ bk,
                       const float* __restrict__ Wv, const float* __restrict__ bv) {
    __shared__ __align__(16) float As[16 * 68];
    __shared__ __align__(16) float Bs[16 * 68];
    const int t  = threadIdx.x;
    const int tx = t & 15, ty = t >> 4;
    const int c0 = blockIdx.x * 64;
    const int r0 = blockIdx.y * 64;
    const int z  = blockIdx.z;
    const float* W = (z == 0) ? Wq : (z == 1) ? Wk : Wv;
    const float* b = (z == 0) ? bq : (z == 1) ? bk : bv;

    float acc[16];
#pragma unroll
    for (int i = 0; i < 16; i++) acc[i] = 0.f;

    for (int kc = 0; kc < DIM; kc += 16) {
#pragma unroll
        for (int i = 0; i < 4; i++) {
            int idx = t + 256 * i;
            int r = idx >> 4, kk = idx & 15;
            As[kk * 68 + r] = X[(size_t)(r0 + r) * DIM + kc + kk];
        }
#pragma unroll
        for (int i = 0; i < 4; i++) {
            int idx = t + 256 * i;
            int kk = idx >> 6, c = idx & 63;
            Bs[kk * 68 + c] = W[(size_t)(kc + kk) * DIM + c0 + c];
        }
        __syncthreads();
#pragma unroll
        for (int kk = 0; kk < 16; kk++) {
            float4 a  = *reinterpret_cast<const float4*>(&As[kk * 68 + ty * 4]);
            float4 bb = *reinterpret_cast<const float4*>(&Bs[kk * 68 + tx * 4]);
            float av[4] = {a.x, a.y, a.z, a.w};
            float bv2[4] = {bb.x, bb.y, bb.z, bb.w};
#pragma unroll
            for (int i = 0; i < 4; i++)
#pragma unroll
                for (int j = 0; j < 4; j++)
                    acc[i * 4 + j] += av[i] * bv2[j];
        }
        __syncthreads();
    }

#pragma unroll
    for (int i = 0; i < 4; i++) {
        int r = r0 + ty * 4 + i;
#pragma unroll
        for (int j = 0; j < 4; j++) {
            int c = c0 + tx * 4 + j;
            float v = acc[i * 4 + j] + b[c];
            int h = c >> 6, d = c & 63;
            __nv_bfloat16 hi = __float2bfloat16(v);
            __nv_bfloat16 lo = __float2bfloat16(v - __bfloat162float(hi));
            if (z == 0) {
                size_t idx = ((size_t)h * NN + r) * HD + d;
                g_Qh[idx] = hi; g_Ql[idx] = lo;
            } else if (z == 1) {
                size_t idx = ((size_t)h * NN + r) * HD + d;
                g_Kh[idx] = hi; g_Kl[idx] = lo;
            } else {
                size_t idx = ((size_t)h * HD + d) * NN + r;   // [h][d][m]
                g_Vh[idx] = hi; g_Vl[idx] = lo;
            }
        }
    }
}

// =====================================================================
// K2: per-edge attention bias GEMM -> g_EA[e][h]
// =====================================================================
__global__ void k_ea(const float* __restrict__ EF,
                     const float* __restrict__ We, const float* __restrict__ be) {
    __shared__ float ef[64][65];
    __shared__ float w[EDIM][NH];
    __shared__ float bsh[NH];
    const int t  = threadIdx.x;
    const int e0 = blockIdx.x * 64;
#pragma unroll
    for (int i = 0; i < 16; i++) {
        int idx = t + 256 * i;
        ef[idx >> 6][idx & 63] = EF[(size_t)e0 * EDIM + idx];
    }
    if (t < EDIM * NH) w[t >> 2][t & 3] = We[t];
    if (t < NH) bsh[t] = be[t];
    __syncthreads();

    const int el = t >> 2, h = t & 3;
    float s = bsh[h];
#pragma unroll
    for (int k = 0; k < EDIM; k++) s += ef[el][k] * w[k][h];
    g_EA[(size_t)(e0 + el) * NH + h] = s;
}

// =====================================================================
// Edge bucketing: key = (src>>7)*64 + (tgt>>6)
// =====================================================================
__global__ void k_bzero() {
    g_bcnt[blockIdx.x * 256 + threadIdx.x] = 0;
}
__global__ void k_hist(const int* __restrict__ EI) {
    int e = blockIdx.x * 256 + threadIdx.x;
    int key = (EI[2 * e] >> 7) * 64 + (EI[2 * e + 1] >> 6);
    atomicAdd(&g_bcnt[key], 1);
}
__global__ void k_scan() {        // one block, 1024 threads, 2048 elements
    __shared__ int s[2048];
    int t = threadIdx.x;
    int c0 = g_bcnt[t], c1 = g_bcnt[t + 1024];
    s[t] = c0; s[t + 1024] = c1;
    __syncthreads();
#pragma unroll 1
    for (int half = 0; half < 2; half++) {
        int* a = s + half * 1024;
        for (int off = 1; off < 1024; off <<= 1) {
            int add = (t >= off) ? a[t - off] : 0;
            __syncthreads();
            a[t] += add;
            __syncthreads();
        }
    }
    int lo_tot = s[1023];
    int incl0 = s[t];
    int incl1 = s[t + 1024] + lo_tot;
    g_boff[t] = incl0 - c0;
    g_boff[t + 1024] = incl1 - c1;
    g_bcur[t] = incl0 - c0;
    g_bcur[t + 1024] = incl1 - c1;
    if (t == 1023) g_boff[2048] = incl1;
}
__global__ void k_scatter(const int* __restrict__ EI) {
    int e = blockIdx.x * 256 + threadIdx.x;
    int key = (EI[2 * e] >> 7) * 64 + (EI[2 * e + 1] >> 6);
    int pos = atomicAdd(&g_bcur[key], 1);
    g_blist[pos] = e;
}

// =====================================================================
// K3: FUSED attention. One CTA per (head, 128-row n-block).
// Loop over 64 m-chunks of 64: QK^T mma -> +10*adj +edge bias -> exp(s-16)
// -> rowsum accumulate -> bf16 hi/lo split -> P@V mma -> O regs.
// Epilogue: scale rows by 1/rowsum.
// smem: QH 16K | QL 16K | KH 8K | KL 8K | VH 8K | VL 8K |
//       S 128x68 f32 34816 | PH 16K | PL 16K | SUMS 512
// =====================================================================
#define FS_QH  0
#define FS_QL  16384
#define FS_KH  32768
#define FS_KL  40960
#define FS_VH  49152
#define FS_VL  57344
#define FS_S   65536
#define FS_PH  100352
#define FS_PL  116736
#define FS_SUM 133120
#define FS_SMEM 133632
#define EXPC   16.0f

__global__ void __launch_bounds__(256, 1) k_fused(const float* __restrict__ adj,
                                                  const int* __restrict__ EI) {
    extern __shared__ char smem[];
    const int t = threadIdx.x, lane = t & 31, wid = t >> 5;
    const int h = blockIdx.x, nb = blockIdx.y, n0 = nb * 128;
    const uint32_t sQH = smem_to_u32(smem);
    const uint32_t sQL = sQH + FS_QL, sKH = sQH + FS_KH, sKL = sQH + FS_KL;
    const uint32_t sVH = sQH + FS_VH, sVL = sQH + FS_VL;
    const uint32_t sPH = sQH + FS_PH, sPL = sQH + FS_PL;
    float* Ss   = (float*)(smem + FS_S);
    float* sums = (float*)(smem + FS_SUM);

    // ---- load Q block once (SW128) ----
    {
        const uint4* qh = (const uint4*)(g_Qh + ((size_t)h * NN + n0) * HD);
        const uint4* ql = (const uint4*)(g_Ql + ((size_t)h * NN + n0) * HD);
#pragma unroll
        for (int i = 0; i < 4; i++) {
            int e = t + 256 * i;
            uint32_t sw = SW128((uint32_t)e * 16);
            *(uint4*)(smem + FS_QH + sw) = qh[e];
            *(uint4*)(smem + FS_QL + sw) = ql[e];
        }
    }

    const __nv_bfloat16* Khb = g_Kh + (size_t)h * NN * HD;
    const __nv_bfloat16* Klb = g_Kl + (size_t)h * NN * HD;
    const __nv_bfloat16* Vhb = g_Vh + (size_t)h * HD * NN;
    const __nv_bfloat16* Vlb = g_Vl + (size_t)h * HD * NN;

    const int g  = lane >> 2, tg = lane & 3;
    const int rl = wid * 16 + g;                 // local row (+8 second group)
    const uint32_t aRow = wid * 16 + (lane & 15);
    const uint32_t cOff = (lane >> 4) * 16;
    const int vr = (t + 0) >> 3;                 // V staging row pattern base

    // ---- prefetch chunk 0 (K/V/adj) into regs ----
    uint4 kh[2], kl[2], vh[2], vl[2];
#pragma unroll
    for (int i = 0; i < 2; i++) {
        int e = t + 256 * i;
        kh[i] = *(const uint4*)(Khb + (size_t)e * 8);
        kl[i] = *(const uint4*)(Klb + (size_t)e * 8);
        int r = e >> 3, c = e & 7;
        vh[i] = *(const uint4*)(Vhb + (size_t)r * NN + c * 8);
        vl[i] = *(const uint4*)(Vlb + (size_t)r * NN + c * 8);
    }
    float2 adjr[8][2];
#pragma unroll
    for (int fm = 0; fm < 8; fm++) {
        int col = fm * 8 + tg * 2;
        adjr[fm][0] = *(const float2*)(adj + (size_t)(n0 + rl) * NN + col);
        adjr[fm][1] = *(const float2*)(adj + (size_t)(n0 + rl + 8) * NN + col);
    }

    float oacc[8][4];
#pragma unroll
    for (int fd = 0; fd < 8; fd++)
#pragma unroll
        for (int k = 0; k < 4; k++) oacc[fd][k] = 0.f;
    float rowsum = 0.f;

    for (int j = 0; j < 64; j++) {
        const int m0 = j * 64;
        // store K/V regs -> smem
#pragma unroll
        for (int i = 0; i < 2; i++) {
            int e = t + 256 * i;
            uint32_t sw = SW128((uint32_t)e * 16);
            *(uint4*)(smem + FS_KH + sw) = kh[i];
            *(uint4*)(smem + FS_KL + sw) = kl[i];
            *(uint4*)(smem + FS_VH + sw) = vh[i];
            *(uint4*)(smem + FS_VL + sw) = vl[i];
        }
        __syncthreads();

        // prefetch next K/V
        if (j < 63) {
            const int m1 = m0 + 64;
#pragma unroll
            for (int i = 0; i < 2; i++) {
                int e = t + 256 * i;
                kh[i] = *(const uint4*)(Khb + (size_t)m1 * HD + (size_t)e * 8);
                kl[i] = *(const uint4*)(Klb + (size_t)m1 * HD + (size_t)e * 8);
                int r = e >> 3, c = e & 7;
                vh[i] = *(const uint4*)(Vhb + (size_t)r * NN + m1 + c * 8);
                vl[i] = *(const uint4*)(Vlb + (size_t)r * NN + m1 + c * 8);
            }
        }

        // ---- QK^T MMA (hi/lo, 3 products) ----
        float qk[8][4];
#pragma unroll
        for (int fm = 0; fm < 8; fm++)
#pragma unroll
            for (int k = 0; k < 4; k++) qk[fm][k] = 0.f;
#pragma unroll
        for (int ks = 0; ks < 4; ks++) {
            uint32_t aH[4], aL[4], bH[4][4], bL[4][4];
            uint32_t byte = aRow * 128 + ks * 32 + cOff;
            ldsm4(aH, sQH + SW128(byte));
            ldsm4(aL, sQL + SW128(byte));
#pragma unroll
            for (int fg = 0; fg < 4; fg++) {
                uint32_t bb = (fg * 16 + (lane & 15)) * 128 + ks * 32 + cOff;
                ldsm4(bH[fg], sKH + SW128(bb));
                ldsm4(bL[fg], sKL + SW128(bb));
            }
#pragma unroll
            for (int fg = 0; fg < 4; fg++) {
                mma_bf16(qk[2*fg],   aH, bH[fg][0], bH[fg][2]);
                mma_bf16(qk[2*fg],   aH, bL[fg][0], bL[fg][2]);
                mma_bf16(qk[2*fg],   aL, bH[fg][0], bH[fg][2]);
                mma_bf16(qk[2*fg+1], aH, bH[fg][1], bH[fg][3]);
                mma_bf16(qk[2*fg+1], aH, bL[fg][1], bL[fg][3]);
                mma_bf16(qk[2*fg+1], aL, bH[fg][1], bH[fg][3]);
            }
        }

        // ---- s = 0.125*qk + 10*adj -> smem (stride 68) ----
#pragma unroll
        for (int fm = 0; fm < 8; fm++) {
            int col = fm * 8 + tg * 2;
            Ss[rl * 68 + col]           = qk[fm][0] * 0.125f + 10.f * adjr[fm][0].x;
            Ss[rl * 68 + col + 1]       = qk[fm][1] * 0.125f + 10.f * adjr[fm][0].y;
            Ss[(rl + 8) * 68 + col]     = qk[fm][2] * 0.125f + 10.f * adjr[fm][1].x;
            Ss[(rl + 8) * 68 + col + 1] = qk[fm][3] * 0.125f + 10.f * adjr[fm][1].y;
        }
        // prefetch next adj (after consumption)
        if (j < 63) {
            const int m1 = m0 + 64;
#pragma unroll
            for (int fm = 0; fm < 8; fm++) {
                int col = m1 + fm * 8 + tg * 2;
                adjr[fm][0] = *(const float2*)(adj + (size_t)(n0 + rl) * NN + col);
                adjr[fm][1] = *(const float2*)(adj + (size_t)(n0 + rl + 8) * NN + col);
            }
        }
        __syncthreads();

        // ---- edge bias apply ----
        {
            int b = nb * 64 + j;
            int o0 = g_boff[b], o1 = g_boff[b + 1];
            for (int i = o0 + t; i < o1; i += 256) {
                int e = g_blist[i];
                int src = EI[2 * e], tgt = EI[2 * e + 1];
                atomicAdd(&Ss[(src & 127) * 68 + (tgt & 63)],
                          g_EA[(size_t)e * NH + h]);
            }
        }
        __syncthreads();

        // ---- exp + rowsum + bf16 hi/lo split -> P smem ----
        {
            int r = t >> 1, c0 = (t & 1) * 32;
            const float* srow = Ss + r * 68 + c0;
#pragma unroll
            for (int q = 0; q < 8; q++) {
                float4 v = *(const float4*)(srow + q * 4);
                float p0 = __expf(v.x - EXPC), p1 = __expf(v.y - EXPC);
                float p2 = __expf(v.z - EXPC), p3 = __expf(v.w - EXPC);
                rowsum += (p0 + p1) + (p2 + p3);
                __nv_bfloat16 h0 = __float2bfloat16(p0), h1 = __float2bfloat16(p1);
                __nv_bfloat16 h2 = __float2bfloat16(p2), h3 = __float2bfloat16(p3);
                uint2 hv, lv;
                { __nv_bfloat162 u; u.x = h0; u.y = h1; hv.x = *(uint32_t*)&u;
                  u.x = h2; u.y = h3; hv.y = *(uint32_t*)&u; }
                lv.x = pack_bf16f(p0 - __bfloat162float(h0), p1 - __bfloat162float(h1));
                lv.y = pack_bf16f(p2 - __bfloat162float(h2), p3 - __bfloat162float(h3));
                uint32_t sw = SW128((uint32_t)(r * 128 + (c0 + q * 4) * 2));
                *(uint2*)(smem + FS_PH + sw) = hv;
                *(uint2*)(smem + FS_PL + sw) = lv;
            }
        }
        __syncthreads();

        // ---- P @ V MMA ----
#pragma unroll
        for (int ks = 0; ks < 4; ks++) {
            uint32_t aH[4], aL[4], bH[4][4], bL[4][4];
            uint32_t byte = aRow * 128 + ks * 32 + cOff;
            ldsm4(aH, sPH + SW128(byte));
            ldsm4(aL, sPL + SW128(byte));
#pragma unroll
            for (int fg = 0; fg < 4; fg++) {
                uint32_t bb = (fg * 16 + (lane & 15)) * 128 + ks * 32 + cOff;
                ldsm4(bH[fg], sVH + SW128(bb));
                ldsm4(bL[fg], sVL + SW128(bb));
            }
#pragma unroll
            for (int fg = 0; fg < 4; fg++) {
                mma_bf16(oacc[2*fg],   aH, bH[fg][0], bH[fg][2]);
                mma_bf16(oacc[2*fg],   aH, bL[fg][0], bL[fg][2]);
                mma_bf16(oacc[2*fg],   aL, bH[fg][0], bH[fg][2]);
                mma_bf16(oacc[2*fg+1], aH, bH[fg][1], bH[fg][3]);
                mma_bf16(oacc[2*fg+1], aH, bL[fg][1], bL[fg][3]);
                mma_bf16(oacc[2*fg+1], aL, bH[fg][1], bH[fg][3]);
            }
        }
        __syncthreads();
    }

    // ---- row sums -> smem ----
    rowsum += __shfl_xor_sync(0xffffffffu, rowsum, 1);
    sums[t >> 1] = rowsum;
    __syncthreads();

    // ---- epilogue: scale and write O ----
    const float ri0 = 1.f / sums[rl];
    const float ri8 = 1.f / sums[rl + 8];
    float* dst0 = g_O + (size_t)(n0 + rl) * DIM + h * HD;
    float* dst8 = g_O + (size_t)(n0 + rl + 8) * DIM + h * HD;
#pragma unroll
    for (int fd = 0; fd < 8; fd++) {
        int col = fd * 8 + tg * 2;
        float2 o0 = { oacc[fd][0] * ri0, oacc[fd][1] * ri0 };
        float2 o1 = { oacc[fd][2] * ri8, oacc[fd][3] * ri8 };
        *(float2*)(dst0 + col) = o0;
        *(float2*)(dst8 + col) = o1;
    }
}

// =====================================================================
// K4: g_X2 = g_O @ Wo + bo + X
// =====================================================================
__global__ void k_oproj(const float* __restrict__ Wo, const float* __restrict__ bo,
                        const float* __restrict__ X) {
    __shared__ __align__(16) float As[16 * 68];
    __shared__ __align__(16) float Bs[16 * 68];
    const int t  = threadIdx.x;
    const int tx = t & 15, ty = t >> 4;
    const int c0 = blockIdx.x * 64;
    const int r0 = blockIdx.y * 64;

    float acc[16];
#pragma unroll
    for (int i = 0; i < 16; i++) acc[i] = 0.f;

    for (int kc = 0; kc < DIM; kc += 16) {
#pragma unroll
        for (int i = 0; i < 4; i++) {
            int idx = t + 256 * i;
            int r = idx >> 4, kk = idx & 15;
            As[kk * 68 + r] = g_O[(size_t)(r0 + r) * DIM + kc + kk];
        }
#pragma unroll
        for (int i = 0; i < 4; i++) {
            int idx = t + 256 * i;
            int kk = idx >> 6, c = idx & 63;
            Bs[kk * 68 + c] = Wo[(size_t)(kc + kk) * DIM + c0 + c];
        }
        __syncthreads();
#pragma unroll
        for (int kk = 0; kk < 16; kk++) {
            float4 a  = *reinterpret_cast<const float4*>(&As[kk * 68 + ty * 4]);
            float4 bb = *reinterpret_cast<const float4*>(&Bs[kk * 68 + tx * 4]);
            float av[4] = {a.x, a.y, a.z, a.w};
            float bv2[4] = {bb.x, bb.y, bb.z, bb.w};
#pragma unroll
            for (int i = 0; i < 4; i++)
#pragma unroll
                for (int j = 0; j < 4; j++)
                    acc[i * 4 + j] += av[i] * bv2[j];
        }
        __syncthreads();
    }

#pragma unroll
    for (int i = 0; i < 4; i++) {
        int r = r0 + ty * 4 + i;
#pragma unroll
        for (int j = 0; j < 4; j++) {
            int c = c0 + tx * 4 + j;
            g_X2[(size_t)r * DIM + c] = acc[i * 4 + j] + bo[c] + X[(size_t)r * DIM + c];
        }
    }
}

// =====================================================================
// K5: LayerNorm
// =====================================================================
__device__ __forceinline__ float blk_red(float v, float* red, bool do_max) {
    const int lane = threadIdx.x & 31, wid = threadIdx.x >> 5;
#pragma unroll
    for (int o = 16; o; o >>= 1) {
        float u = __shfl_xor_sync(0xffffffffu, v, o);
        v = do_max ? fmaxf(v, u) : (v + u);
    }
    if (lane == 0) red[wid] = v;
    __syncthreads();
    if (wid == 0) {
        float s = (lane < 8) ? red[lane] : (do_max ? -3.4e38f : 0.f);
#pragma unroll
        for (int o = 4; o; o >>= 1) {
            float u = __shfl_xor_sync(0xffffffffu, s, o);
            s = do_max ? fmaxf(s, u) : (s + u);
        }
        if (lane == 0) red[0] = s;
    }
    __syncthreads();
    float r = red[0];
    __syncthreads();
    return r;
}

__global__ void k_ln(const float* __restrict__ gamma, const float* __restrict__ beta,
                     float* __restrict__ out) {
    __shared__ float red[8];
    const int t = threadIdx.x;
    const int n = blockIdx.x;
    float x = g_X2[(size_t)n * DIM + t];
    float mu = blk_red(x, red, false) * (1.f / DIM);
    float d = x - mu;
    float var = blk_red(d * d, red, false) * (1.f / DIM);
    out[(size_t)n * DIM + t] = gamma[t] * d * rsqrtf(var + LN_EPS) + beta[t];
}

// =====================================================================
extern "C" void kernel_launch(void* const* d_in, const int* in_sizes, int n_in,
                              void* d_out, int out_size) {
    const float* X    = (const float*)d_in[0];
    const float* adj  = (const float*)d_in[1];
    const float* EF   = (const float*)d_in[2];
    const int*   EI   = (const int*)  d_in[3];
    const float* Wq   = (const float*)d_in[4];
    const float* bq   = (const float*)d_in[5];
    const float* Wk   = (const float*)d_in[6];
    const float* bk   = (const float*)d_in[7];
    const float* Wv   = (const float*)d_in[8];
    const float* bv   = (const float*)d_in[9];
    const float* We   = (const float*)d_in[10];
    const float* be   = (const float*)d_in[11];
    const float* Wo   = (const float*)d_in[12];
    const float* bo   = (const float*)d_in[13];
    const float* gam  = (const float*)d_in[14];
    const float* bet  = (const float*)d_in[15];
    float* out = (float*)d_out;

    cudaFuncSetAttribute(k_fused, cudaFuncAttributeMaxDynamicSharedMemorySize, FS_SMEM);

    k_proj   <<<dim3(4, 64, 3), 256>>>(X, Wq, bq, Wk, bk, Wv, bv);
    k_ea     <<<NE / 64, 256>>>(EF, We, be);
    k_bzero  <<<8, 256>>>();
    k_hist   <<<NE / 256, 256>>>(EI);
    k_scan   <<<1, 1024>>>();
    k_scatter<<<NE / 256, 256>>>(EI);
    k_fused  <<<dim3(NH, 32), 256, FS_SMEM>>>(adj, EI);
    k_oproj  <<<dim3(4, 64), 256>>>(Wo, bo, X);
    k_ln     <<<NN, 256>>>(gam, bet, out);
}

// round 6
// speedup vs baseline: 2.1203x; 1.1023x over previous
#include <cuda_runtime.h>
#include <cuda_bf16.h>
#include <cstdint>

#define NN   4096
#define DIM  256
#define NH   4
#define HD   64
#define NE   131072
#define EDIM 64
#define LN_EPS 1e-5f

// ---------------- device scratch ----------------
__device__ __nv_bfloat16 g_Qh[NH * NN * HD], g_Ql[NH * NN * HD];  // [h][n][d]
__device__ __nv_bfloat16 g_Kh[NH * NN * HD], g_Kl[NH * NN * HD];  // [h][m][d]
__device__ __nv_bfloat16 g_Vh[NH * HD * NN], g_Vl[NH * HD * NN];  // [h][d][m]
__device__ float g_EA[(size_t)NE * NH];     // per-edge attn bias [e][h]
__device__ int   g_bcnt[2048];              // bucket histogram (nb*64 + mchunk)
__device__ int   g_boff[2049];              // exclusive offsets
__device__ int   g_bcur[2048];              // scatter cursors
__device__ int   g_blist[NE];               // bucketed edge ids
__device__ float g_O[NN * DIM];
__device__ float g_X2[NN * DIM];

// ---------------- helpers ----------------
__device__ __forceinline__ uint32_t smem_to_u32(const void* p) {
    uint32_t a;
    asm("{ .reg .u64 t; cvta.to.shared.u64 t, %1; cvt.u32.u64 %0, t; }" : "=r"(a) : "l"(p));
    return a;
}
#define SW128(b) ((b) ^ (((b) >> 3) & 0x70))

__device__ __forceinline__ void ldsm4(uint32_t r[4], uint32_t addr) {
    asm volatile("ldmatrix.sync.aligned.m8n8.x4.shared.b16 {%0,%1,%2,%3}, [%4];"
        : "=r"(r[0]), "=r"(r[1]), "=r"(r[2]), "=r"(r[3]) : "r"(addr));
}
__device__ __forceinline__ void mma_bf16(float c[4], const uint32_t a[4],
                                         uint32_t b0, uint32_t b1) {
    asm volatile("mma.sync.aligned.m16n8k16.row.col.f32.bf16.bf16.f32 "
        "{%0,%1,%2,%3}, {%4,%5,%6,%7}, {%8,%9}, {%0,%1,%2,%3};"
        : "+f"(c[0]), "+f"(c[1]), "+f"(c[2]), "+f"(c[3])
        : "r"(a[0]), "r"(a[1]), "r"(a[2]), "r"(a[3]), "r"(b0), "r"(b1));
}
__device__ __forceinline__ uint32_t pack_bf16f(float a, float b) {
    __nv_bfloat162 t;
    t.x = __float2bfloat16(a);
    t.y = __float2bfloat16(b);
    return *reinterpret_cast<uint32_t*>(&t);
}

// =====================================================================
// K1: fused QKV projection -> bf16 hi/lo splits. Also zeros g_bcnt.
// =====================================================================
__global__ void k_proj(const float* __restrict__ X,
                       const float* __restrict__ Wq, const float* __restrict__ bq,
                       const float* __restrict__ Wk, const float* __restrict__ bk,
                       const float* __restrict__ Wv, const float* __restrict__ bv) {
    __shared__ __align__(16) float As[16 * 68];
    __shared__ __align__(16) float Bs[16 * 68];
    const int t  = threadIdx.x;
    const int tx = t & 15, ty = t >> 4;
    const int c0 = blockIdx.x * 64;
    const int r0 = blockIdx.y * 64;
    const int z  = blockIdx.z;
    if (z == 0 && blockIdx.x == 0 && blockIdx.y < 8)
        g_bcnt[blockIdx.y * 256 + t] = 0;
    const float* W = (z == 0) ? Wq : (z == 1) ? Wk : Wv;
    const float* b = (z == 0) ? bq : (z == 1) ? bk : bv;

    float acc[16];
#pragma unroll
    for (int i = 0; i < 16; i++) acc[i] = 0.f;

    for (int kc = 0; kc < DIM; kc += 16) {
#pragma unroll
        for (int i = 0; i < 4; i++) {
            int idx = t + 256 * i;
            int r = idx >> 4, kk = idx & 15;
            As[kk * 68 + r] = X[(size_t)(r0 + r) * DIM + kc + kk];
        }
#pragma unroll
        for (int i = 0; i < 4; i++) {
            int idx = t + 256 * i;
            int kk = idx >> 6, c = idx & 63;
            Bs[kk * 68 + c] = W[(size_t)(kc + kk) * DIM + c0 + c];
        }
        __syncthreads();
#pragma unroll
        for (int kk = 0; kk < 16; kk++) {
            float4 a  = *reinterpret_cast<const float4*>(&As[kk * 68 + ty * 4]);
            float4 bb = *reinterpret_cast<const float4*>(&Bs[kk * 68 + tx * 4]);
            float av[4] = {a.x, a.y, a.z, a.w};
            float bv2[4] = {bb.x, bb.y, bb.z, bb.w};
#pragma unroll
            for (int i = 0; i < 4; i++)
#pragma unroll
                for (int j = 0; j < 4; j++)
                    acc[i * 4 + j] += av[i] * bv2[j];
        }
        __syncthreads();
    }

#pragma unroll
    for (int i = 0; i < 4; i++) {
        int r = r0 + ty * 4 + i;
#pragma unroll
        for (int j = 0; j < 4; j++) {
            int c = c0 + tx * 4 + j;
            float v = acc[i * 4 + j] + b[c];
            int h = c >> 6, d = c & 63;
            __nv_bfloat16 hi = __float2bfloat16(v);
            __nv_bfloat16 lo = __float2bfloat16(v - __bfloat162float(hi));
            if (z == 0) {
                size_t idx = ((size_t)h * NN + r) * HD + d;
                g_Qh[idx] = hi; g_Ql[idx] = lo;
            } else if (z == 1) {
                size_t idx = ((size_t)h * NN + r) * HD + d;
                g_Kh[idx] = hi; g_Kl[idx] = lo;
            } else {
                size_t idx = ((size_t)h * HD + d) * NN + r;   // [h][d][m]
                g_Vh[idx] = hi; g_Vl[idx] = lo;
            }
        }
    }
}

// =====================================================================
// K2: per-edge attention bias GEMM -> g_EA[e][h]; also edge histogram.
// =====================================================================
__global__ void k_ea(const float* __restrict__ EF, const int* __restrict__ EI,
                     const float* __restrict__ We, const float* __restrict__ be) {
    __shared__ float ef[64][65];
    __shared__ float w[EDIM][NH];
    __shared__ float bsh[NH];
    const int t  = threadIdx.x;
    const int e0 = blockIdx.x * 64;
#pragma unroll
    for (int i = 0; i < 16; i++) {
        int idx = t + 256 * i;
        ef[idx >> 6][idx & 63] = EF[(size_t)e0 * EDIM + idx];
    }
    if (t < EDIM * NH) w[t >> 2][t & 3] = We[t];
    if (t < NH) bsh[t] = be[t];
    __syncthreads();

    const int el = t >> 2, h = t & 3;
    const int e = e0 + el;
    float s = bsh[h];
#pragma unroll
    for (int k = 0; k < EDIM; k++) s += ef[el][k] * w[k][h];
    g_EA[(size_t)e * NH + h] = s;
    if (h == 0) {
        int key = (EI[2 * e] >> 7) * 64 + ((EI[2 * e + 1] >> 6) & 63);
        atomicAdd(&g_bcnt[key], 1);
    }
}

// =====================================================================
// Edge bucketing scan + scatter
// =====================================================================
__global__ void k_scan() {        // one block, 1024 threads, 2048 elements
    __shared__ int s[2048];
    int t = threadIdx.x;
    int c0 = g_bcnt[t], c1 = g_bcnt[t + 1024];
    s[t] = c0; s[t + 1024] = c1;
    __syncthreads();
#pragma unroll 1
    for (int half = 0; half < 2; half++) {
        int* a = s + half * 1024;
        for (int off = 1; off < 1024; off <<= 1) {
            int add = (t >= off) ? a[t - off] : 0;
            __syncthreads();
            a[t] += add;
            __syncthreads();
        }
    }
    int lo_tot = s[1023];
    int incl0 = s[t];
    int incl1 = s[t + 1024] + lo_tot;
    g_boff[t] = incl0 - c0;
    g_boff[t + 1024] = incl1 - c1;
    g_bcur[t] = incl0 - c0;
    g_bcur[t + 1024] = incl1 - c1;
    if (t == 1023) g_boff[2048] = incl1;
}
__global__ void k_scatter(const int* __restrict__ EI) {
    int e = blockIdx.x * 256 + threadIdx.x;
    int key = (EI[2 * e] >> 7) * 64 + ((EI[2 * e + 1] >> 6) & 63);
    int pos = atomicAdd(&g_bcur[key], 1);
    g_blist[pos] = e;
}

// =====================================================================
// K3: FUSED attention v2. 512 threads / 16 warps. CTA = (head, 128-row nb).
// Warp (wr = w&7, wc = w>>3): rows 16*wr..+15, cols 32*wc..+31.
// Q fragments in registers; Q smem region reused as P buffer 0.
// Double-buffered KV / P / E; 2 syncthreads per m-chunk.
// smem map (bytes):
//   [0,16K)    QH -> P0H       [16K,32K)  QL -> P0L
//   [32K,48K)  P1H             [48K,64K)  P1L
//   [64K+32K*b) KH,KL,VH,VL (8K each), b in {0,1}
//   [128K+33K*b) E tile 128x66 fp32
//   [194K]     sums[2][128]
// =====================================================================
#define FB_KV(b)  (65536u + (b) * 32768u)
#define FB_E(b)   (131072u + (b) * 33792u)
#define FB_SUM    198656u
#define FS_SMEM   199680
#define EXPC      16.0f

__global__ void __launch_bounds__(512, 1) k_fused(const float* __restrict__ adj,
                                                  const int* __restrict__ EI) {
    extern __shared__ char smem[];
    const uint32_t sb = smem_to_u32(smem);
    const int t = threadIdx.x, lane = t & 31, w = t >> 5;
    const int wr = w & 7, wc = w >> 3;
    const int h = blockIdx.x, nb = blockIdx.y, n0 = nb * 128;

    const int g  = lane >> 2, tg = lane & 3;
    const int rl = wr * 16 + g;
    const uint32_t aRow = wr * 16 + (lane & 15);
    const uint32_t cOff = (lane >> 4) * 16;

    const __nv_bfloat16* Khb = g_Kh + (size_t)h * NN * HD;
    const __nv_bfloat16* Klb = g_Kl + (size_t)h * NN * HD;
    const __nv_bfloat16* Vhb = g_Vh + (size_t)h * HD * NN;
    const __nv_bfloat16* Vlb = g_Vl + (size_t)h * HD * NN;

    // ---------- prologue ----------
    // Q tile (128 x 64 hi/lo) -> smem [0,32K)
    {
        const uint4* qh = (const uint4*)(g_Qh + ((size_t)h * NN + n0) * HD);
        const uint4* ql = (const uint4*)(g_Ql + ((size_t)h * NN + n0) * HD);
#pragma unroll
        for (int i = 0; i < 2; i++) {
            int e = t + 512 * i;
            uint32_t sw = SW128((uint32_t)e * 16);
            *(uint4*)(smem + sw)         = qh[e];
            *(uint4*)(smem + 16384 + sw) = ql[e];
        }
    }
    // KV chunk 0 -> KV[0]
    {
        const int r = t >> 3, c8 = (t & 7) * 8;
        uint32_t sw = SW128((uint32_t)(r * 128 + (t & 7) * 16));
        *(uint4*)(smem + FB_KV(0) + sw)         = *(const uint4*)(Khb + (size_t)r * HD + c8);
        *(uint4*)(smem + FB_KV(0) + 8192 + sw)  = *(const uint4*)(Klb + (size_t)r * HD + c8);
        *(uint4*)(smem + FB_KV(0) + 16384 + sw) = *(const uint4*)(Vhb + (size_t)r * NN + c8);
        *(uint4*)(smem + FB_KV(0) + 24576 + sw) = *(const uint4*)(Vlb + (size_t)r * NN + c8);
    }
    // zero E[0]
    {
        uint4 z = make_uint4(0, 0, 0, 0);
        uint4* E0 = (uint4*)(smem + FB_E(0));
        for (int i = t; i < 2112; i += 512) E0[i] = z;
    }
    // adj prefetch chunk 0
    float2 adjr[4][2];
#pragma unroll
    for (int fi = 0; fi < 4; fi++) {
        int col = wc * 32 + fi * 8 + tg * 2;
        adjr[fi][0] = *(const float2*)(adj + (size_t)(n0 + rl) * NN + col);
        adjr[fi][1] = *(const float2*)(adj + (size_t)(n0 + rl + 8) * NN + col);
    }
    __syncthreads();

    // Q fragments -> registers (Q smem region becomes P0 after this)
    uint32_t aQH[4][4], aQL[4][4];
#pragma unroll
    for (int ks = 0; ks < 4; ks++) {
        uint32_t byte = aRow * 128 + ks * 32 + cOff;
        ldsm4(aQH[ks], sb + SW128(byte));
        ldsm4(aQL[ks], sb + 16384 + SW128(byte));
    }

    float oacc[4][4];
#pragma unroll
    for (int fi = 0; fi < 4; fi++)
#pragma unroll
        for (int k = 0; k < 4; k++) oacc[fi][k] = 0.f;
    float rowsum0 = 0.f, rowsum8 = 0.f;
    uint4 khv, klv, vhv, vlv;

    for (int j = 0; j < 64; j++) {
        const int b = j & 1;
        const uint32_t kvOff = FB_KV(b);
        const uint32_t sKH = sb + kvOff, sKL = sKH + 8192;
        const uint32_t sVH = sKH + 16384, sVL = sKH + 24576;
        const uint32_t pHOff = b ? 32768u : 0u;
        const uint32_t pLOff = pHOff + 16384u;
        const uint32_t sPH = sb + pHOff, sPL = sb + pLOff;
        float* Et = (float*)(smem + FB_E(b));

        // ---- phase A: edge scatter + QK MMA + KV prefetch ----
        {
            int bkt = nb * 64 + j;
            int o0 = g_boff[bkt], o1 = g_boff[bkt + 1];
            for (int i = o0 + t; i < o1; i += 512) {
                int e = g_blist[i];
                atomicAdd(&Et[(EI[2 * e] & 127) * 66 + (EI[2 * e + 1] & 63)],
                          g_EA[(size_t)e * NH + h]);
            }
        }
        float qk[4][4];
#pragma unroll
        for (int fi = 0; fi < 4; fi++)
#pragma unroll
            for (int k = 0; k < 4; k++) qk[fi][k] = 0.f;
#pragma unroll
        for (int ks = 0; ks < 4; ks++) {
            uint32_t bH[2][4], bL[2][4];
#pragma unroll
            for (int fg = 0; fg < 2; fg++) {
                uint32_t bb = (wc * 32 + fg * 16 + (lane & 15)) * 128 + ks * 32 + cOff;
                ldsm4(bH[fg], sKH + SW128(bb));
                ldsm4(bL[fg], sKL + SW128(bb));
            }
#pragma unroll
            for (int fg = 0; fg < 2; fg++) {
                mma_bf16(qk[2*fg],   aQH[ks], bH[fg][0], bH[fg][2]);
                mma_bf16(qk[2*fg],   aQH[ks], bL[fg][0], bL[fg][2]);
                mma_bf16(qk[2*fg],   aQL[ks], bH[fg][0], bH[fg][2]);
                mma_bf16(qk[2*fg+1], aQH[ks], bH[fg][1], bH[fg][3]);
                mma_bf16(qk[2*fg+1], aQH[ks], bL[fg][1], bL[fg][3]);
                mma_bf16(qk[2*fg+1], aQL[ks], bH[fg][1], bH[fg][3]);
            }
        }
        if (j < 63) {
            const int m1 = (j + 1) * 64;
            const int r = t >> 3, c8 = (t & 7) * 8;
            khv = *(const uint4*)(Khb + (size_t)(m1 + r) * HD + c8);
            klv = *(const uint4*)(Klb + (size_t)(m1 + r) * HD + c8);
            vhv = *(const uint4*)(Vhb + (size_t)r * NN + m1 + c8);
            vlv = *(const uint4*)(Vlb + (size_t)r * NN + m1 + c8);
        }
        __syncthreads();

        // ---- phase B: fragments -> exp -> P ; store KV[b^1]; zero E[b^1] ----
#pragma unroll
        for (int fi = 0; fi < 4; fi++) {
            int col = wc * 32 + fi * 8 + tg * 2;
            float2 e0 = *(const float2*)(Et + rl * 66 + col);
            float2 e8 = *(const float2*)(Et + (rl + 8) * 66 + col);
            float p0 = __expf(qk[fi][0] * 0.125f + 10.f * adjr[fi][0].x + e0.x - EXPC);
            float p1 = __expf(qk[fi][1] * 0.125f + 10.f * adjr[fi][0].y + e0.y - EXPC);
            float p2 = __expf(qk[fi][2] * 0.125f + 10.f * adjr[fi][1].x + e8.x - EXPC);
            float p3 = __expf(qk[fi][3] * 0.125f + 10.f * adjr[fi][1].y + e8.y - EXPC);
            rowsum0 += p0 + p1;
            rowsum8 += p2 + p3;
            __nv_bfloat16 h0 = __float2bfloat16(p0), h1 = __float2bfloat16(p1);
            __nv_bfloat16 h2 = __float2bfloat16(p2), h3 = __float2bfloat16(p3);
            uint32_t hv0, hv8;
            { __nv_bfloat162 u; u.x = h0; u.y = h1; hv0 = *(uint32_t*)&u;
              u.x = h2; u.y = h3; hv8 = *(uint32_t*)&u; }
            uint32_t lv0 = pack_bf16f(p0 - __bfloat162float(h0), p1 - __bfloat162float(h1));
            uint32_t lv8 = pack_bf16f(p2 - __bfloat162float(h2), p3 - __bfloat162float(h3));
            uint32_t sw0 = SW128((uint32_t)(rl * 128 + col * 2));
            uint32_t sw8 = SW128((uint32_t)((rl + 8) * 128 + col * 2));
            *(uint32_t*)(smem + pHOff + sw0) = hv0;
            *(uint32_t*)(smem + pHOff + sw8) = hv8;
            *(uint32_t*)(smem + pLOff + sw0) = lv0;
            *(uint32_t*)(smem + pLOff + sw8) = lv8;
        }
        if (j < 63) {
            uint32_t sw = SW128((uint32_t)((t >> 3) * 128 + (t & 7) * 16));
            *(uint4*)(smem + FB_KV(b ^ 1) + sw)         = khv;
            *(uint4*)(smem + FB_KV(b ^ 1) + 8192 + sw)  = klv;
            *(uint4*)(smem + FB_KV(b ^ 1) + 16384 + sw) = vhv;
            *(uint4*)(smem + FB_KV(b ^ 1) + 24576 + sw) = vlv;
            uint4 z = make_uint4(0, 0, 0, 0);
            uint4* En = (uint4*)(smem + FB_E(b ^ 1));
            for (int i = t; i < 2112; i += 512) En[i] = z;
            const int m1 = (j + 1) * 64;
#pragma unroll
            for (int fi = 0; fi < 4; fi++) {
                int col = m1 + wc * 32 + fi * 8 + tg * 2;
                adjr[fi][0] = *(const float2*)(adj + (size_t)(n0 + rl) * NN + col);
                adjr[fi][1] = *(const float2*)(adj + (size_t)(n0 + rl + 8) * NN + col);
            }
        }
        __syncthreads();

        // ---- phase C: P @ V MMA ----
#pragma unroll
        for (int ks = 0; ks < 4; ks++) {
            uint32_t aH[4], aL[4], bH[2][4], bL[2][4];
            uint32_t byte = aRow * 128 + ks * 32 + cOff;
            ldsm4(aH, sPH + SW128(byte));
            ldsm4(aL, sPL + SW128(byte));
#pragma unroll
            for (int fg = 0; fg < 2; fg++) {
                uint32_t bb = (wc * 32 + fg * 16 + (lane & 15)) * 128 + ks * 32 + cOff;
                ldsm4(bH[fg], sVH + SW128(bb));
                ldsm4(bL[fg], sVL + SW128(bb));
            }
#pragma unroll
            for (int fg = 0; fg < 2; fg++) {
                mma_bf16(oacc[2*fg],   aH, bH[fg][0], bH[fg][2]);
                mma_bf16(oacc[2*fg],   aH, bL[fg][0], bL[fg][2]);
                mma_bf16(oacc[2*fg],   aL, bH[fg][0], bH[fg][2]);
                mma_bf16(oacc[2*fg+1], aH, bH[fg][1], bH[fg][3]);
                mma_bf16(oacc[2*fg+1], aH, bL[fg][1], bL[fg][3]);
                mma_bf16(oacc[2*fg+1], aL, bH[fg][1], bH[fg][3]);
            }
        }
    }

    // ---- epilogue: rowsums across col-halves, scale, write O ----
    rowsum0 += __shfl_xor_sync(0xffffffffu, rowsum0, 1);
    rowsum0 += __shfl_xor_sync(0xffffffffu, rowsum0, 2);
    rowsum8 += __shfl_xor_sync(0xffffffffu, rowsum8, 1);
    rowsum8 += __shfl_xor_sync(0xffffffffu, rowsum8, 2);
    float* sums = (float*)(smem + FB_SUM);
    if (tg == 0) {
        sums[wc * 128 + rl] = rowsum0;
        sums[wc * 128 + rl + 8] = rowsum8;
    }
    __syncthreads();
    const float ri0 = 1.f / (sums[rl] + sums[128 + rl]);
    const float ri8 = 1.f / (sums[rl + 8] + sums[128 + rl + 8]);
    float* dst0 = g_O + (size_t)(n0 + rl) * DIM + h * HD + wc * 32;
    float* dst8 = g_O + (size_t)(n0 + rl + 8) * DIM + h * HD + wc * 32;
#pragma unroll
    for (int fi = 0; fi < 4; fi++) {
        int col = fi * 8 + tg * 2;
        float2 o0 = { oacc[fi][0] * ri0, oacc[fi][1] * ri0 };
        float2 o1 = { oacc[fi][2] * ri8, oacc[fi][3] * ri8 };
        *(float2*)(dst0 + col) = o0;
        *(float2*)(dst8 + col) = o1;
    }
}

// =====================================================================
// K4: g_X2 = g_O @ Wo + bo + X
// =====================================================================
__global__ void k_oproj(const float* __restrict__ Wo, const float* __restrict__ bo,
                        const float* __restrict__ X) {
    __shared__ __align__(16) float As[16 * 68];
    __shared__ __align__(16) float Bs[16 * 68];
    const int t  = threadIdx.x;
    const int tx = t & 15, ty = t >> 4;
    const int c0 = blockIdx.x * 64;
    const int r0 = blockIdx.y * 64;

    float acc[16];
#pragma unroll
    for (int i = 0; i < 16; i++) acc[i] = 0.f;

    for (int kc = 0; kc < DIM; kc += 16) {
#pragma unroll
        for (int i = 0; i < 4; i++) {
            int idx = t + 256 * i;
            int r = idx >> 4, kk = idx & 15;
            As[kk * 68 + r] = g_O[(size_t)(r0 + r) * DIM + kc + kk];
        }
#pragma unroll
        for (int i = 0; i < 4; i++) {
            int idx = t + 256 * i;
            int kk = idx >> 6, c = idx & 63;
            Bs[kk * 68 + c] = Wo[(size_t)(kc + kk) * DIM + c0 + c];
        }
        __syncthreads();
#pragma unroll
        for (int kk = 0; kk < 16; kk++) {
            float4 a  = *reinterpret_cast<const float4*>(&As[kk * 68 + ty * 4]);
            float4 bb = *reinterpret_cast<const float4*>(&Bs[kk * 68 + tx * 4]);
            float av[4] = {a.x, a.y, a.z, a.w};
            float bv2[4] = {bb.x, bb.y, bb.z, bb.w};
#pragma unroll
            for (int i = 0; i < 4; i++)
#pragma unroll
                for (int j = 0; j < 4; j++)
                    acc[i * 4 + j] += av[i] * bv2[j];
        }
        __syncthreads();
    }

#pragma unroll
    for (int i = 0; i < 4; i++) {
        int r = r0 + ty * 4 + i;
#pragma unroll
        for (int j = 0; j < 4; j++) {
            int c = c0 + tx * 4 + j;
            g_X2[(size_t)r * DIM + c] = acc[i * 4 + j] + bo[c] + X[(size_t)r * DIM + c];
        }
    }
}

// =====================================================================
// K5: LayerNorm
// =====================================================================
__device__ __forceinline__ float blk_red(float v, float* red) {
    const int lane = threadIdx.x & 31, wid = threadIdx.x >> 5;
#pragma unroll
    for (int o = 16; o; o >>= 1) v += __shfl_xor_sync(0xffffffffu, v, o);
    if (lane == 0) red[wid] = v;
    __syncthreads();
    if (wid == 0) {
        float s = (lane < 8) ? red[lane] : 0.f;
#pragma unroll
        for (int o = 4; o; o >>= 1) s += __shfl_xor_sync(0xffffffffu, s, o);
        if (lane == 0) red[0] = s;
    }
    __syncthreads();
    float r = red[0];
    __syncthreads();
    return r;
}

__global__ void k_ln(const float* __restrict__ gamma, const float* __restrict__ beta,
                     float* __restrict__ out) {
    __shared__ float red[8];
    const int t = threadIdx.x;
    const int n = blockIdx.x;
    float x = g_X2[(size_t)n * DIM + t];
    float mu = blk_red(x, red) * (1.f / DIM);
    float d = x - mu;
    float var = blk_red(d * d, red) * (1.f / DIM);
    out[(size_t)n * DIM + t] = gamma[t] * d * rsqrtf(var + LN_EPS) + beta[t];
}

// =====================================================================
extern "C" void kernel_launch(void* const* d_in, const int* in_sizes, int n_in,
                              void* d_out, int out_size) {
    const float* X    = (const float*)d_in[0];
    const float* adj  = (const float*)d_in[1];
    const float* EF   = (const float*)d_in[2];
    const int*   EI   = (const int*)  d_in[3];
    const float* Wq   = (const float*)d_in[4];
    const float* bq   = (const float*)d_in[5];
    const float* Wk   = (const float*)d_in[6];
    const float* bk   = (const float*)d_in[7];
    const float* Wv   = (const float*)d_in[8];
    const float* bv   = (const float*)d_in[9];
    const float* We   = (const float*)d_in[10];
    const float* be   = (const float*)d_in[11];
    const float* Wo   = (const float*)d_in[12];
    const float* bo   = (const float*)d_in[13];
    const float* gam  = (const float*)d_in[14];
    const float* bet  = (const float*)d_in[15];
    float* out = (float*)d_out;

    cudaFuncSetAttribute(k_fused, cudaFuncAttributeMaxDynamicSharedMemorySize, FS_SMEM);

    k_proj   <<<dim3(4, 64, 3), 256>>>(X, Wq, bq, Wk, bk, Wv, bv);
    k_ea     <<<NE / 64, 256>>>(EF, EI, We, be);
    k_scan   <<<1, 1024>>>();
    k_scatter<<<NE / 256, 256>>>(EI);
    k_fused  <<<dim3(NH, 32), 512, FS_SMEM>>>(adj, EI);
    k_oproj  <<<dim3(4, 64), 256>>>(Wo, bo, X);
    k_ln     <<<NN, 256>>>(gam, bet, out);
}

// round 7
// speedup vs baseline: 2.3811x; 1.1230x over previous
#include <cuda_runtime.h>
#include <cuda_bf16.h>
#include <cstdint>

#define NN   4096
#define DIM  256
#define NH   4
#define HD   64
#define NE   131072
#define EDIM 64
#define LN_EPS 1e-5f

// ---------------- device scratch ----------------
__device__ __nv_bfloat16 g_Qh[NH * NN * HD], g_Ql[NH * NN * HD];  // [h][n][d]
__device__ __nv_bfloat16 g_Kh[NH * NN * HD], g_Kl[NH * NN * HD];  // [h][m][d]
__device__ __nv_bfloat16 g_Vh[NH * HD * NN], g_Vl[NH * HD * NN];  // [h][d][m]
__device__ float g_EA[(size_t)NE * NH];
__device__ int   g_bcnt[2048];
__device__ int   g_boff[2049];
__device__ int   g_bcur[2048];
__device__ int   g_blist[NE];
__device__ float g_O[NN * DIM];
__device__ float g_X2[NN * DIM];

// ---------------- helpers ----------------
__device__ __forceinline__ uint32_t smem_to_u32(const void* p) {
    uint32_t a;
    asm("{ .reg .u64 t; cvta.to.shared.u64 t, %1; cvt.u32.u64 %0, t; }" : "=r"(a) : "l"(p));
    return a;
}
#define SW128(b) ((b) ^ (((b) >> 3) & 0x70))
#define CP_ASYNC16(dst, src) \
    asm volatile("cp.async.cg.shared.global [%0], [%1], 16;" :: "r"(dst), "l"(src))
#define CP_COMMIT() asm volatile("cp.async.commit_group;" ::: "memory")
#define CP_WAIT0()  asm volatile("cp.async.wait_group 0;" ::: "memory")

__device__ __forceinline__ void ldsm4(uint32_t r[4], uint32_t addr) {
    asm volatile("ldmatrix.sync.aligned.m8n8.x4.shared.b16 {%0,%1,%2,%3}, [%4];"
        : "=r"(r[0]), "=r"(r[1]), "=r"(r[2]), "=r"(r[3]) : "r"(addr));
}
__device__ __forceinline__ void mma_bf16(float c[4], const uint32_t a[4],
                                         uint32_t b0, uint32_t b1) {
    asm volatile("mma.sync.aligned.m16n8k16.row.col.f32.bf16.bf16.f32 "
        "{%0,%1,%2,%3}, {%4,%5,%6,%7}, {%8,%9}, {%0,%1,%2,%3};"
        : "+f"(c[0]), "+f"(c[1]), "+f"(c[2]), "+f"(c[3])
        : "r"(a[0]), "r"(a[1]), "r"(a[2]), "r"(a[3]), "r"(b0), "r"(b1));
}
__device__ __forceinline__ uint32_t pack_bf16f(float a, float b) {
    __nv_bfloat162 t;
    t.x = __float2bfloat16(a);
    t.y = __float2bfloat16(b);
    return *reinterpret_cast<uint32_t*>(&t);
}

// =====================================================================
// K1: fused QKV projection -> bf16 hi/lo splits. Also zeros g_bcnt.
// =====================================================================
__global__ void k_proj(const float* __restrict__ X,
                       const float* __restrict__ Wq, const float* __restrict__ bq,
                       const float* __restrict__ Wk, const float* __restrict__ bk,
                       const float* __restrict__ Wv, const float* __restrict__ bv) {
    __shared__ __align__(16) float As[16 * 68];
    __shared__ __align__(16) float Bs[16 * 68];
    const int t  = threadIdx.x;
    const int tx = t & 15, ty = t >> 4;
    const int c0 = blockIdx.x * 64;
    const int r0 = blockIdx.y * 64;
    const int z  = blockIdx.z;
    if (z == 0 && blockIdx.x == 0 && blockIdx.y < 8)
        g_bcnt[blockIdx.y * 256 + t] = 0;
    const float* W = (z == 0) ? Wq : (z == 1) ? Wk : Wv;
    const float* b = (z == 0) ? bq : (z == 1) ? bk : bv;

    float acc[16];
#pragma unroll
    for (int i = 0; i < 16; i++) acc[i] = 0.f;

    for (int kc = 0; kc < DIM; kc += 16) {
#pragma unroll
        for (int i = 0; i < 4; i++) {
            int idx = t + 256 * i;
            int r = idx >> 4, kk = idx & 15;
            As[kk * 68 + r] = X[(size_t)(r0 + r) * DIM + kc + kk];
        }
#pragma unroll
        for (int i = 0; i < 4; i++) {
            int idx = t + 256 * i;
            int kk = idx >> 6, c = idx & 63;
            Bs[kk * 68 + c] = W[(size_t)(kc + kk) * DIM + c0 + c];
        }
        __syncthreads();
#pragma unroll
        for (int kk = 0; kk < 16; kk++) {
            float4 a  = *reinterpret_cast<const float4*>(&As[kk * 68 + ty * 4]);
            float4 bb = *reinterpret_cast<const float4*>(&Bs[kk * 68 + tx * 4]);
            float av[4] = {a.x, a.y, a.z, a.w};
            float bv2[4] = {bb.x, bb.y, bb.z, bb.w};
#pragma unroll
            for (int i = 0; i < 4; i++)
#pragma unroll
                for (int j = 0; j < 4; j++)
                    acc[i * 4 + j] += av[i] * bv2[j];
        }
        __syncthreads();
    }

#pragma unroll
    for (int i = 0; i < 4; i++) {
        int r = r0 + ty * 4 + i;
#pragma unroll
        for (int j = 0; j < 4; j++) {
            int c = c0 + tx * 4 + j;
            float v = acc[i * 4 + j] + b[c];
            int h = c >> 6, d = c & 63;
            __nv_bfloat16 hi = __float2bfloat16(v);
            __nv_bfloat16 lo = __float2bfloat16(v - __bfloat162float(hi));
            if (z == 0) {
                size_t idx = ((size_t)h * NN + r) * HD + d;
                g_Qh[idx] = hi; g_Ql[idx] = lo;
            } else if (z == 1) {
                size_t idx = ((size_t)h * NN + r) * HD + d;
                g_Kh[idx] = hi; g_Kl[idx] = lo;
            } else {
                size_t idx = ((size_t)h * HD + d) * NN + r;
                g_Vh[idx] = hi; g_Vl[idx] = lo;
            }
        }
    }
}

// =====================================================================
// K2: per-edge attention bias GEMM -> g_EA[e][h]; also edge histogram.
// =====================================================================
__global__ void k_ea(const float* __restrict__ EF, const int* __restrict__ EI,
                     const float* __restrict__ We, const float* __restrict__ be) {
    __shared__ float ef[64][65];
    __shared__ float w[EDIM][NH];
    __shared__ float bsh[NH];
    const int t  = threadIdx.x;
    const int e0 = blockIdx.x * 64;
#pragma unroll
    for (int i = 0; i < 16; i++) {
        int idx = t + 256 * i;
        ef[idx >> 6][idx & 63] = EF[(size_t)e0 * EDIM + idx];
    }
    if (t < EDIM * NH) w[t >> 2][t & 3] = We[t];
    if (t < NH) bsh[t] = be[t];
    __syncthreads();

    const int el = t >> 2, h = t & 3;
    const int e = e0 + el;
    float s = bsh[h];
#pragma unroll
    for (int k = 0; k < EDIM; k++) s += ef[el][k] * w[k][h];
    g_EA[(size_t)e * NH + h] = s;
    if (h == 0) {
        int key = (EI[2 * e] >> 7) * 64 + ((EI[2 * e + 1] >> 6) & 63);
        atomicAdd(&g_bcnt[key], 1);
    }
}

// =====================================================================
// Edge bucketing scan + scatter
// =====================================================================
__global__ void k_scan() {
    __shared__ int s[2048];
    int t = threadIdx.x;
    int c0 = g_bcnt[t], c1 = g_bcnt[t + 1024];
    s[t] = c0; s[t + 1024] = c1;
    __syncthreads();
#pragma unroll 1
    for (int half = 0; half < 2; half++) {
        int* a = s + half * 1024;
        for (int off = 1; off < 1024; off <<= 1) {
            int add = (t >= off) ? a[t - off] : 0;
            __syncthreads();
            a[t] += add;
            __syncthreads();
        }
    }
    int lo_tot = s[1023];
    int incl0 = s[t];
    int incl1 = s[t + 1024] + lo_tot;
    g_boff[t] = incl0 - c0;
    g_boff[t + 1024] = incl1 - c1;
    g_bcur[t] = incl0 - c0;
    g_bcur[t + 1024] = incl1 - c1;
    if (t == 1023) g_boff[2048] = incl1;
}
__global__ void k_scatter(const int* __restrict__ EI) {
    int e = blockIdx.x * 256 + threadIdx.x;
    int key = (EI[2 * e] >> 7) * 64 + ((EI[2 * e + 1] >> 6) & 63);
    int pos = atomicAdd(&g_bcur[key], 1);
    g_blist[pos] = e;
}

// =====================================================================
// K3: FUSED attention v3. 512 threads / 16 warps. CTA = (head, 128-row nb).
// Warp (wr=w&7, wc=w>>3): QK rows 16wr x m-cols 32wc..+31.
// P stays in registers (QK C-frag == PV A-frag layout); each warp does
// P[16x32] @ V[32x64] partial; cross-wc O reduce in epilogue.
// KV + adj double-buffered via cp.async. 2 syncthreads / iter.
// smem: ADJ(b)=b*34816 (128x68 f32)  [Q prologue borrows ADJ0]
//       KV(b)=69632+b*32768 (KH,KL,VH,VL 8K each)
//       E(b)=135168+b*33792 (128x66 f32)
//       sums @202752 (256 f32)  total 203776
// =====================================================================
#define FB_ADJ(b) ((b) * 34816u)
#define FB_KV(b)  (69632u + (b) * 32768u)
#define FB_E(b)   (135168u + (b) * 33792u)
#define FB_SUM    202752u
#define FS_SMEM   203776
#define EXPC      16.0f

__global__ void __launch_bounds__(512, 1) k_fused(const float* __restrict__ adj,
                                                  const int* __restrict__ EI) {
    extern __shared__ char smem[];
    const uint32_t sb = smem_to_u32(smem);
    const int t = threadIdx.x, lane = t & 31, w = t >> 5;
    const int wr = w & 7, wc = w >> 3;
    const int h = blockIdx.x, nb = blockIdx.y, n0 = nb * 128;

    const int g  = lane >> 2, tg = lane & 3;
    const int rl = wr * 16 + g;
    const uint32_t aRow = wr * 16 + (lane & 15);
    const uint32_t cOff = (lane >> 4) * 16;

    const __nv_bfloat16* Khb = g_Kh + (size_t)h * NN * HD;
    const __nv_bfloat16* Klb = g_Kl + (size_t)h * NN * HD;
    const __nv_bfloat16* Vhb = g_Vh + (size_t)h * HD * NN;
    const __nv_bfloat16* Vlb = g_Vl + (size_t)h * HD * NN;

    // ---------- prologue ----------
    const int kvr = t >> 3, kvc = t & 7;          // KV cp.async mapping
    const uint32_t kvsw = SW128((uint32_t)(kvr * 128 + kvc * 16));
    // KV chunk 0
    CP_ASYNC16(sb + FB_KV(0) + kvsw,          Khb + (size_t)kvr * HD + kvc * 8);
    CP_ASYNC16(sb + FB_KV(0) + 8192 + kvsw,   Klb + (size_t)kvr * HD + kvc * 8);
    CP_ASYNC16(sb + FB_KV(0) + 16384 + kvsw,  Vhb + (size_t)kvr * NN + kvc * 8);
    CP_ASYNC16(sb + FB_KV(0) + 24576 + kvsw,  Vlb + (size_t)kvr * NN + kvc * 8);
    CP_COMMIT();
    // Q tile (borrow ADJ0 region)
    {
        const uint4* qh = (const uint4*)(g_Qh + ((size_t)h * NN + n0) * HD);
        const uint4* ql = (const uint4*)(g_Ql + ((size_t)h * NN + n0) * HD);
#pragma unroll
        for (int i = 0; i < 2; i++) {
            int e = t + 512 * i;
            uint32_t sw = SW128((uint32_t)e * 16);
            *(uint4*)(smem + sw)         = qh[e];
            *(uint4*)(smem + 16384 + sw) = ql[e];
        }
    }
    // zero E(0)
    {
        uint4 z = make_uint4(0, 0, 0, 0);
        uint4* E0 = (uint4*)(smem + FB_E(0));
        for (int i = t; i < 2112; i += 512) E0[i] = z;
    }
    __syncthreads();

    uint32_t aQH[4][4], aQL[4][4];
#pragma unroll
    for (int ks = 0; ks < 4; ks++) {
        uint32_t byte = aRow * 128 + ks * 32 + cOff;
        ldsm4(aQH[ks], sb + SW128(byte));
        ldsm4(aQL[ks], sb + 16384 + SW128(byte));
    }
    __syncthreads();   // Q region now free -> ADJ0

    // adj chunk 0 -> ADJ(0)
    const int ajr = t >> 4, ajc = t & 15;         // 4 iters: rows ajr+32i? no: idx map
#pragma unroll
    for (int i = 0; i < 4; i++) {
        int idx = t + 512 * i;
        int row = idx >> 4, c4 = idx & 15;
        CP_ASYNC16(sb + FB_ADJ(0) + (uint32_t)(row * 272 + c4 * 16),
                   adj + (size_t)(n0 + row) * NN + c4 * 4);
    }
    CP_COMMIT();
    CP_WAIT0();
    __syncthreads();

    float oacc[8][4];
#pragma unroll
    for (int fd = 0; fd < 8; fd++)
#pragma unroll
        for (int k = 0; k < 4; k++) oacc[fd][k] = 0.f;
    float rowsum0 = 0.f, rowsum8 = 0.f;

    for (int j = 0; j < 64; j++) {
        const int b = j & 1;
        const uint32_t sKH = sb + FB_KV(b), sKL = sKH + 8192;
        const uint32_t sVH = sKH + 16384,  sVL = sKH + 24576;
        float* Et = (float*)(smem + FB_E(b));
        float* At = (float*)(smem + FB_ADJ(b));

        // ---- phase A: edge scatter into E(b); QK mma; cp.async next ----
        {
            int bkt = nb * 64 + j;
            int o0 = g_boff[bkt], o1 = g_boff[bkt + 1];
            for (int i = o0 + t; i < o1; i += 512) {
                int e = g_blist[i];
                atomicAdd(&Et[(EI[2 * e] & 127) * 66 + (EI[2 * e + 1] & 63)],
                          g_EA[(size_t)e * NH + h]);
            }
        }
        float qk[4][4];
#pragma unroll
        for (int fi = 0; fi < 4; fi++)
#pragma unroll
            for (int k = 0; k < 4; k++) qk[fi][k] = 0.f;
#pragma unroll
        for (int ks = 0; ks < 4; ks++) {
            uint32_t bH[2][4], bL[2][4];
#pragma unroll
            for (int fg = 0; fg < 2; fg++) {
                uint32_t bb = (wc * 32 + fg * 16 + (lane & 15)) * 128 + ks * 32 + cOff;
                ldsm4(bH[fg], sKH + SW128(bb));
                ldsm4(bL[fg], sKL + SW128(bb));
            }
#pragma unroll
            for (int fg = 0; fg < 2; fg++) {
                mma_bf16(qk[2*fg],   aQH[ks], bH[fg][0], bH[fg][2]);
                mma_bf16(qk[2*fg],   aQH[ks], bL[fg][0], bL[fg][2]);
                mma_bf16(qk[2*fg],   aQL[ks], bH[fg][0], bH[fg][2]);
                mma_bf16(qk[2*fg+1], aQH[ks], bH[fg][1], bH[fg][3]);
                mma_bf16(qk[2*fg+1], aQH[ks], bL[fg][1], bL[fg][3]);
                mma_bf16(qk[2*fg+1], aQL[ks], bH[fg][1], bH[fg][3]);
            }
        }
        if (j < 63) {
            const int m1 = (j + 1) * 64;
            CP_ASYNC16(sb + FB_KV(b ^ 1) + kvsw,         Khb + (size_t)(m1 + kvr) * HD + kvc * 8);
            CP_ASYNC16(sb + FB_KV(b ^ 1) + 8192 + kvsw,  Klb + (size_t)(m1 + kvr) * HD + kvc * 8);
            CP_ASYNC16(sb + FB_KV(b ^ 1) + 16384 + kvsw, Vhb + (size_t)kvr * NN + m1 + kvc * 8);
            CP_ASYNC16(sb + FB_KV(b ^ 1) + 24576 + kvsw, Vlb + (size_t)kvr * NN + m1 + kvc * 8);
#pragma unroll
            for (int i = 0; i < 4; i++) {
                int idx = t + 512 * i;
                int row = idx >> 4, c4 = idx & 15;
                CP_ASYNC16(sb + FB_ADJ(b ^ 1) + (uint32_t)(row * 272 + c4 * 16),
                           adj + (size_t)(n0 + row) * NN + m1 + c4 * 4);
            }
            CP_COMMIT();
        }
        __syncthreads();   // SYNC1: E(b) scatter complete

        // ---- phase B: exp -> P regs; P@V mma; zero E(b^1); wait cp.async ----
        uint32_t pH0[4], pH8[4], pL0[4], pL8[4];
#pragma unroll
        for (int fi = 0; fi < 4; fi++) {
            int col = wc * 32 + fi * 8 + tg * 2;
            float2 a0 = *(const float2*)(At + rl * 68 + col);
            float2 a8 = *(const float2*)(At + (rl + 8) * 68 + col);
            float2 e0 = *(const float2*)(Et + rl * 66 + col);
            float2 e8 = *(const float2*)(Et + (rl + 8) * 66 + col);
            float p0 = __expf(qk[fi][0] * 0.125f + 10.f * a0.x + e0.x - EXPC);
            float p1 = __expf(qk[fi][1] * 0.125f + 10.f * a0.y + e0.y - EXPC);
            float p2 = __expf(qk[fi][2] * 0.125f + 10.f * a8.x + e8.x - EXPC);
            float p3 = __expf(qk[fi][3] * 0.125f + 10.f * a8.y + e8.y - EXPC);
            rowsum0 += p0 + p1;
            rowsum8 += p2 + p3;
            __nv_bfloat16 h0 = __float2bfloat16(p0), h1 = __float2bfloat16(p1);
            __nv_bfloat16 h2 = __float2bfloat16(p2), h3 = __float2bfloat16(p3);
            { __nv_bfloat162 u; u.x = h0; u.y = h1; pH0[fi] = *(uint32_t*)&u;
              u.x = h2; u.y = h3; pH8[fi] = *(uint32_t*)&u; }
            pL0[fi] = pack_bf16f(p0 - __bfloat162float(h0), p1 - __bfloat162float(h1));
            pL8[fi] = pack_bf16f(p2 - __bfloat162float(h2), p3 - __bfloat162float(h3));
        }
        // P @ V: k-steps over warp's own 32 m-cols; n = all 64 d
#pragma unroll
        for (int ks2 = 0; ks2 < 2; ks2++) {
            uint32_t aH[4] = {pH0[2*ks2], pH8[2*ks2], pH0[2*ks2+1], pH8[2*ks2+1]};
            uint32_t aL[4] = {pL0[2*ks2], pL8[2*ks2], pL0[2*ks2+1], pL8[2*ks2+1]};
#pragma unroll
            for (int fg = 0; fg < 4; fg++) {
                uint32_t bb = (fg * 16 + (lane & 15)) * 128 + wc * 64 + ks2 * 32 + cOff;
                uint32_t bH[4], bL[4];
                ldsm4(bH, sVH + SW128(bb));
                ldsm4(bL, sVL + SW128(bb));
                mma_bf16(oacc[2*fg],   aH, bH[0], bH[2]);
                mma_bf16(oacc[2*fg],   aH, bL[0], bL[2]);
                mma_bf16(oacc[2*fg],   aL, bH[0], bH[2]);
                mma_bf16(oacc[2*fg+1], aH, bH[1], bH[3]);
                mma_bf16(oacc[2*fg+1], aH, bL[1], bL[3]);
                mma_bf16(oacc[2*fg+1], aL, bH[1], bH[3]);
            }
        }
        if (j < 63) {
            uint4 z = make_uint4(0, 0, 0, 0);
            uint4* En = (uint4*)(smem + FB_E(b ^ 1));
            for (int i = t; i < 2112; i += 512) En[i] = z;
        }
        CP_WAIT0();
        __syncthreads();   // SYNC2
    }

    // ---- epilogue ----
    rowsum0 += __shfl_xor_sync(0xffffffffu, rowsum0, 1);
    rowsum0 += __shfl_xor_sync(0xffffffffu, rowsum0, 2);
    rowsum8 += __shfl_xor_sync(0xffffffffu, rowsum8, 1);
    rowsum8 += __shfl_xor_sync(0xffffffffu, rowsum8, 2);
    float* sums = (float*)(smem + FB_SUM);
    if (tg == 0) {
        sums[wc * 128 + rl] = rowsum0;
        sums[wc * 128 + rl + 8] = rowsum8;
    }
    // cross-wc O reduction via ADJ0 region (free now)
    float* buf = (float*)(smem + FB_ADJ(0));
    __syncthreads();
    if (wc == 1) {
#pragma unroll
        for (int fd = 0; fd < 8; fd++) {
            int col = (fd >> 1) * 16 + (fd & 1) * 8 + tg * 2;
            buf[rl * 68 + col]           = oacc[fd][0];
            buf[rl * 68 + col + 1]       = oacc[fd][1];
            buf[(rl + 8) * 68 + col]     = oacc[fd][2];
            buf[(rl + 8) * 68 + col + 1] = oacc[fd][3];
        }
    }
    __syncthreads();
    if (wc == 0) {
        const float ri0 = 1.f / (sums[rl] + sums[128 + rl]);
        const float ri8 = 1.f / (sums[rl + 8] + sums[128 + rl + 8]);
        float* dst0 = g_O + (size_t)(n0 + rl) * DIM + h * HD;
        float* dst8 = g_O + (size_t)(n0 + rl + 8) * DIM + h * HD;
#pragma unroll
        for (int fd = 0; fd < 8; fd++) {
            int col = (fd >> 1) * 16 + (fd & 1) * 8 + tg * 2;
            float2 o0 = { (oacc[fd][0] + buf[rl * 68 + col]) * ri0,
                          (oacc[fd][1] + buf[rl * 68 + col + 1]) * ri0 };
            float2 o1 = { (oacc[fd][2] + buf[(rl + 8) * 68 + col]) * ri8,
                          (oacc[fd][3] + buf[(rl + 8) * 68 + col + 1]) * ri8 };
            *(float2*)(dst0 + col) = o0;
            *(float2*)(dst8 + col) = o1;
        }
    }
}

// =====================================================================
// K4: g_X2 = g_O @ Wo + bo + X
// =====================================================================
__global__ void k_oproj(const float* __restrict__ Wo, const float* __restrict__ bo,
                        const float* __restrict__ X) {
    __shared__ __align__(16) float As[16 * 68];
    __shared__ __align__(16) float Bs[16 * 68];
    const int t  = threadIdx.x;
    const int tx = t & 15, ty = t >> 4;
    const int c0 = blockIdx.x * 64;
    const int r0 = blockIdx.y * 64;

    float acc[16];
#pragma unroll
    for (int i = 0; i < 16; i++) acc[i] = 0.f;

    for (int kc = 0; kc < DIM; kc += 16) {
#pragma unroll
        for (int i = 0; i < 4; i++) {
            int idx = t + 256 * i;
            int r = idx >> 4, kk = idx & 15;
            As[kk * 68 + r] = g_O[(size_t)(r0 + r) * DIM + kc + kk];
        }
#pragma unroll
        for (int i = 0; i < 4; i++) {
            int idx = t + 256 * i;
            int kk = idx >> 6, c = idx & 63;
            Bs[kk * 68 + c] = Wo[(size_t)(kc + kk) * DIM + c0 + c];
        }
        __syncthreads();
#pragma unroll
        for (int kk = 0; kk < 16; kk++) {
            float4 a  = *reinterpret_cast<const float4*>(&As[kk * 68 + ty * 4]);
            float4 bb = *reinterpret_cast<const float4*>(&Bs[kk * 68 + tx * 4]);
            float av[4] = {a.x, a.y, a.z, a.w};
            float bv2[4] = {bb.x, bb.y, bb.z, bb.w};
#pragma unroll
            for (int i = 0; i < 4; i++)
#pragma unroll
                for (int j = 0; j < 4; j++)
                    acc[i * 4 + j] += av[i] * bv2[j];
        }
        __syncthreads();
    }

#pragma unroll
    for (int i = 0; i < 4; i++) {
        int r = r0 + ty * 4 + i;
#pragma unroll
        for (int j = 0; j < 4; j++) {
            int c = c0 + tx * 4 + j;
            g_X2[(size_t)r * DIM + c] = acc[i * 4 + j] + bo[c] + X[(size_t)r * DIM + c];
        }
    }
}

// =====================================================================
// K5: LayerNorm
// =====================================================================
__device__ __forceinline__ float blk_red(float v, float* red) {
    const int lane = threadIdx.x & 31, wid = threadIdx.x >> 5;
#pragma unroll
    for (int o = 16; o; o >>= 1) v += __shfl_xor_sync(0xffffffffu, v, o);
    if (lane == 0) red[wid] = v;
    __syncthreads();
    if (wid == 0) {
        float s = (lane < 8) ? red[lane] : 0.f;
#pragma unroll
        for (int o = 4; o; o >>= 1) s += __shfl_xor_sync(0xffffffffu, s, o);
        if (lane == 0) red[0] = s;
    }
    __syncthreads();
    float r = red[0];
    __syncthreads();
    return r;
}

__global__ void k_ln(const float* __restrict__ gamma, const float* __restrict__ beta,
                     float* __restrict__ out) {
    __shared__ float red[8];
    const int t = threadIdx.x;
    const int n = blockIdx.x;
    float x = g_X2[(size_t)n * DIM + t];
    float mu = blk_red(x, red) * (1.f / DIM);
    float d = x - mu;
    float var = blk_red(d * d, red) * (1.f / DIM);
    out[(size_t)n * DIM + t] = gamma[t] * d * rsqrtf(var + LN_EPS) + beta[t];
}

// =====================================================================
extern "C" void kernel_launch(void* const* d_in, const int* in_sizes, int n_in,
                              void* d_out, int out_size) {
    const float* X    = (const float*)d_in[0];
    const float* adj  = (const float*)d_in[1];
    const float* EF   = (const float*)d_in[2];
    const int*   EI   = (const int*)  d_in[3];
    const float* Wq   = (const float*)d_in[4];
    const float* bq   = (const float*)d_in[5];
    const float* Wk   = (const float*)d_in[6];
    const float* bk   = (const float*)d_in[7];
    const float* Wv   = (const float*)d_in[8];
    const float* bv   = (const float*)d_in[9];
    const float* We   = (const float*)d_in[10];
    const float* be   = (const float*)d_in[11];
    const float* Wo   = (const float*)d_in[12];
    const float* bo   = (const float*)d_in[13];
    const float* gam  = (const float*)d_in[14];
    const float* bet  = (const float*)d_in[15];
    float* out = (float*)d_out;

    cudaFuncSetAttribute(k_fused, cudaFuncAttributeMaxDynamicSharedMemorySize, FS_SMEM);

    k_proj   <<<dim3(4, 64, 3), 256>>>(X, Wq, bq, Wk, bk, Wv, bv);
    k_ea     <<<NE / 64, 256>>>(EF, EI, We, be);
    k_scan   <<<1, 1024>>>();
    k_scatter<<<NE / 256, 256>>>(EI);
    k_fused  <<<dim3(NH, 32), 512, FS_SMEM>>>(adj, EI);
    k_oproj  <<<dim3(4, 64), 256>>>(Wo, bo, X);
    k_ln     <<<NN, 256>>>(gam, bet, out);
}

// round 8
// speedup vs baseline: 2.5679x; 1.0784x over previous
#include <cuda_runtime.h>
#include <cuda_bf16.h>
#include <cstdint>

#define NN   4096
#define DIM  256
#define NH   4
#define HD   64
#define NE   131072
#define EDIM 64
#define LN_EPS 1e-5f
#define BCAP 192

#define QSC  0.18033688011112042f     // 0.125 * log2(e)
#define C10  14.426950408889634f      // 10 * log2(e)
#define CB  -23.083120654223414f      // -16 * log2(e)
#define L2E  1.4426950408889634f

// ---------------- device scratch ----------------
__device__ __nv_bfloat16 g_Qh[NH * NN * HD], g_Ql[NH * NN * HD];  // [h][n][d] (scaled)
__device__ __nv_bfloat16 g_Kh[NH * NN * HD], g_Kl[NH * NN * HD];  // [h][m][d]
__device__ __nv_bfloat16 g_Vh[NH * HD * NN], g_Vl[NH * HD * NN];  // [h][d][m]
__device__ float g_EA[(size_t)NE * NH];       // log2e-scaled edge bias
__device__ int   g_bcnt[2048];
__device__ int   g_blist[2048 * BCAP];
__device__ int   g_pad;
__device__ float g_O[NN * DIM];
__device__ float g_X2[NN * DIM];

// ---------------- helpers ----------------
__device__ __forceinline__ uint32_t smem_to_u32(const void* p) {
    uint32_t a;
    asm("{ .reg .u64 t; cvta.to.shared.u64 t, %1; cvt.u32.u64 %0, t; }" : "=r"(a) : "l"(p));
    return a;
}
#define SW128(b) ((b) ^ (((b) >> 3) & 0x70))
#define CP_ASYNC16(dst, src) \
    asm volatile("cp.async.cg.shared.global [%0], [%1], 16;" :: "r"(dst), "l"(src))
#define CP_COMMIT() asm volatile("cp.async.commit_group;" ::: "memory")
#define CP_WAIT0()  asm volatile("cp.async.wait_group 0;" ::: "memory")

__device__ __forceinline__ void ldsm4(uint32_t r[4], uint32_t addr) {
    asm volatile("ldmatrix.sync.aligned.m8n8.x4.shared.b16 {%0,%1,%2,%3}, [%4];"
        : "=r"(r[0]), "=r"(r[1]), "=r"(r[2]), "=r"(r[3]) : "r"(addr));
}
__device__ __forceinline__ void mma_bf16(float c[4], const uint32_t a[4],
                                         uint32_t b0, uint32_t b1) {
    asm volatile("mma.sync.aligned.m16n8k16.row.col.f32.bf16.bf16.f32 "
        "{%0,%1,%2,%3}, {%4,%5,%6,%7}, {%8,%9}, {%0,%1,%2,%3};"
        : "+f"(c[0]), "+f"(c[1]), "+f"(c[2]), "+f"(c[3])
        : "r"(a[0]), "r"(a[1]), "r"(a[2]), "r"(a[3]), "r"(b0), "r"(b1));
}
__device__ __forceinline__ float ex2(float x) {
    float r;
    asm("ex2.approx.f32 %0, %1;" : "=f"(r) : "f"(x));
    return r;
}
__device__ __forceinline__ uint32_t cvt2(float lo, float hi) {   // pack {lo, hi}
    uint32_t r;
    asm("cvt.rn.bf16x2.f32 %0, %1, %2;" : "=r"(r) : "f"(hi), "f"(lo));
    return r;
}

// =====================================================================
// K1: fused QKV projection -> bf16 hi/lo splits (Q pre-scaled). Zeros g_bcnt.
// =====================================================================
__global__ void k_proj(const float* __restrict__ X,
                       const float* __restrict__ Wq, const float* __restrict__ bq,
                       const float* __restrict__ Wk, const float* __restrict__ bk,
                       const float* __restrict__ Wv, const float* __restrict__ bv) {
    __shared__ __align__(16) float As[16 * 68];
    __shared__ __align__(16) float Bs[16 * 68];
    const int t  = threadIdx.x;
    const int tx = t & 15, ty = t >> 4;
    const int c0 = blockIdx.x * 64;
    const int r0 = blockIdx.y * 64;
    const int z  = blockIdx.z;
    if (z == 0 && blockIdx.x == 0 && blockIdx.y < 8)
        g_bcnt[blockIdx.y * 256 + t] = 0;
    const float* W = (z == 0) ? Wq : (z == 1) ? Wk : Wv;
    const float* b = (z == 0) ? bq : (z == 1) ? bk : bv;

    float acc[16];
#pragma unroll
    for (int i = 0; i < 16; i++) acc[i] = 0.f;

    for (int kc = 0; kc < DIM; kc += 16) {
#pragma unroll
        for (int i = 0; i < 4; i++) {
            int idx = t + 256 * i;
            int r = idx >> 4, kk = idx & 15;
            As[kk * 68 + r] = X[(size_t)(r0 + r) * DIM + kc + kk];
        }
#pragma unroll
        for (int i = 0; i < 4; i++) {
            int idx = t + 256 * i;
            int kk = idx >> 6, c = idx & 63;
            Bs[kk * 68 + c] = W[(size_t)(kc + kk) * DIM + c0 + c];
        }
        __syncthreads();
#pragma unroll
        for (int kk = 0; kk < 16; kk++) {
            float4 a  = *reinterpret_cast<const float4*>(&As[kk * 68 + ty * 4]);
            float4 bb = *reinterpret_cast<const float4*>(&Bs[kk * 68 + tx * 4]);
            float av[4] = {a.x, a.y, a.z, a.w};
            float bv2[4] = {bb.x, bb.y, bb.z, bb.w};
#pragma unroll
            for (int i = 0; i < 4; i++)
#pragma unroll
                for (int j = 0; j < 4; j++)
                    acc[i * 4 + j] += av[i] * bv2[j];
        }
        __syncthreads();
    }

#pragma unroll
    for (int i = 0; i < 4; i++) {
        int r = r0 + ty * 4 + i;
#pragma unroll
        for (int j = 0; j < 4; j++) {
            int c = c0 + tx * 4 + j;
            float v = acc[i * 4 + j] + b[c];
            if (z == 0) v *= QSC;
            int h = c >> 6, d = c & 63;
            __nv_bfloat16 hi = __float2bfloat16(v);
            __nv_bfloat16 lo = __float2bfloat16(v - __bfloat162float(hi));
            if (z == 0) {
                size_t idx = ((size_t)h * NN + r) * HD + d;
                g_Qh[idx] = hi; g_Ql[idx] = lo;
            } else if (z == 1) {
                size_t idx = ((size_t)h * NN + r) * HD + d;
                g_Kh[idx] = hi; g_Kl[idx] = lo;
            } else {
                size_t idx = ((size_t)h * HD + d) * NN + r;
                g_Vh[idx] = hi; g_Vl[idx] = lo;
            }
        }
    }
}

// =====================================================================
// K2: per-edge bias GEMM -> g_EA (log2e-scaled); direct bucket scatter.
// =====================================================================
__global__ void k_ea(const float* __restrict__ EF, const int* __restrict__ EI,
                     const float* __restrict__ We, const float* __restrict__ be) {
    __shared__ float ef[64][65];
    __shared__ float w[EDIM][NH];
    __shared__ float bsh[NH];
    const int t  = threadIdx.x;
    const int e0 = blockIdx.x * 64;
#pragma unroll
    for (int i = 0; i < 16; i++) {
        int idx = t + 256 * i;
        ef[idx >> 6][idx & 63] = EF[(size_t)e0 * EDIM + idx];
    }
    if (t < EDIM * NH) w[t >> 2][t & 3] = We[t];
    if (t < NH) bsh[t] = be[t];
    __syncthreads();

    const int el = t >> 2, h = t & 3;
    const int e = e0 + el;
    float s = bsh[h];
#pragma unroll
    for (int k = 0; k < EDIM; k++) s += ef[el][k] * w[k][h];
    g_EA[(size_t)e * NH + h] = s * L2E;
    if (h == 0) {
        int key = (EI[2 * e] >> 7) * 64 + ((EI[2 * e + 1] >> 6) & 63);
        int pos = atomicAdd(&g_bcnt[key], 1);
        if (pos < BCAP) g_blist[key * BCAP + pos] = e;
    }
}

// padding kernel so k_fused is the 4th launch (ncu captures launch #4)
__global__ void k_pad() { if (threadIdx.x == 0) g_pad = 1; }

// =====================================================================
// K3: FUSED attention v4. 512 threads / 16 warps. CTA = (head, 128-row nb).
// QH frags in regs; QL resident in smem (re-ldsm per k-step).
// exp args pre-folded to base-2; E tile init = CB.
// smem: QL 16K @0 | ADJ(b) @16384+b*34816 | KV(b) @86016+b*32768 |
//       E(b) @151552+b*33792 | sums @219136 ; total 220160
// =====================================================================
#define FB_QL   0u
#define FB_ADJ(b) (16384u + (b) * 34816u)
#define FB_KV(b)  (86016u + (b) * 32768u)
#define FB_E(b)   (151552u + (b) * 33792u)
#define FB_SUM    219136u
#define FS_SMEM   220160

__global__ void __launch_bounds__(512, 1) k_fused(const float* __restrict__ adj,
                                                  const int* __restrict__ EI) {
    extern __shared__ char smem[];
    const uint32_t sb = smem_to_u32(smem);
    const int t = threadIdx.x, lane = t & 31, w = t >> 5;
    const int wr = w & 7, wc = w >> 3;
    const int h = blockIdx.x, nb = blockIdx.y, n0 = nb * 128;

    const int g  = lane >> 2, tg = lane & 3;
    const int rl = wr * 16 + g;
    const uint32_t aRow = wr * 16 + (lane & 15);
    const uint32_t cOff = (lane >> 4) * 16;

    const __nv_bfloat16* Khb = g_Kh + (size_t)h * NN * HD;
    const __nv_bfloat16* Klb = g_Kl + (size_t)h * NN * HD;
    const __nv_bfloat16* Vhb = g_Vh + (size_t)h * HD * NN;
    const __nv_bfloat16* Vlb = g_Vl + (size_t)h * HD * NN;

    // ---------- prologue ----------
    const int kvr = t >> 3, kvc = t & 7;
    const uint32_t kvsw = SW128((uint32_t)(kvr * 128 + kvc * 16));
    CP_ASYNC16(sb + FB_KV(0) + kvsw,          Khb + (size_t)kvr * HD + kvc * 8);
    CP_ASYNC16(sb + FB_KV(0) + 8192 + kvsw,   Klb + (size_t)kvr * HD + kvc * 8);
    CP_ASYNC16(sb + FB_KV(0) + 16384 + kvsw,  Vhb + (size_t)kvr * NN + kvc * 8);
    CP_ASYNC16(sb + FB_KV(0) + 24576 + kvsw,  Vlb + (size_t)kvr * NN + kvc * 8);
    CP_COMMIT();
    // QL -> resident @0 ; QH staged into ADJ(0) area @16384
    {
        const uint4* qh = (const uint4*)(g_Qh + ((size_t)h * NN + n0) * HD);
        const uint4* ql = (const uint4*)(g_Ql + ((size_t)h * NN + n0) * HD);
#pragma unroll
        for (int i = 0; i < 2; i++) {
            int e = t + 512 * i;
            uint32_t sw = SW128((uint32_t)e * 16);
            *(uint4*)(smem + FB_QL + sw)    = ql[e];
            *(uint4*)(smem + 16384u + sw)   = qh[e];
        }
    }
    // init E(0) to CB
    {
        const uint32_t cbb = __float_as_uint(CB);
        uint4 z = make_uint4(cbb, cbb, cbb, cbb);
        uint4* E0 = (uint4*)(smem + FB_E(0));
        for (int i = t; i < 2112; i += 512) E0[i] = z;
    }
    __syncthreads();

    uint32_t aQH[4][4];
#pragma unroll
    for (int ks = 0; ks < 4; ks++) {
        uint32_t byte = aRow * 128 + ks * 32 + cOff;
        ldsm4(aQH[ks], sb + 16384u + SW128(byte));
    }
    __syncthreads();   // QH stage region free -> ADJ(0)

#pragma unroll
    for (int i = 0; i < 4; i++) {
        int idx = t + 512 * i;
        int row = idx >> 4, c4 = idx & 15;
        CP_ASYNC16(sb + FB_ADJ(0) + (uint32_t)(row * 272 + c4 * 16),
                   adj + (size_t)(n0 + row) * NN + c4 * 4);
    }
    CP_COMMIT();
    CP_WAIT0();
    __syncthreads();

    float oacc[8][4];
#pragma unroll
    for (int fd = 0; fd < 8; fd++)
#pragma unroll
        for (int k = 0; k < 4; k++) oacc[fd][k] = 0.f;
    float rowsum0 = 0.f, rowsum8 = 0.f;

    for (int j = 0; j < 64; j++) {
        const int b = j & 1;
        const uint32_t sKH = sb + FB_KV(b), sKL = sKH + 8192;
        const uint32_t sVH = sKH + 16384,  sVL = sKH + 24576;
        float* Et = (float*)(smem + FB_E(b));
        float* At = (float*)(smem + FB_ADJ(b));

        // ---- phase A: edge scatter; QK mma; cp.async next ----
        {
            int key = nb * 64 + j;
            int cnt = g_bcnt[key];
            int base = key * BCAP;
            for (int i = t; i < cnt; i += 512) {
                int e = g_blist[base + i];
                atomicAdd(&Et[(EI[2 * e] & 127) * 66 + (EI[2 * e + 1] & 63)],
                          g_EA[(size_t)e * NH + h]);
            }
        }
        float qk[4][4];
#pragma unroll
        for (int fi = 0; fi < 4; fi++)
#pragma unroll
            for (int k = 0; k < 4; k++) qk[fi][k] = 0.f;
#pragma unroll
        for (int ks = 0; ks < 4; ks++) {
            uint32_t byte = aRow * 128 + ks * 32 + cOff;
            uint32_t aQL[4];
            ldsm4(aQL, sb + FB_QL + SW128(byte));
            uint32_t bH[2][4], bL[2][4];
#pragma unroll
            for (int fg = 0; fg < 2; fg++) {
                uint32_t bb = (wc * 32 + fg * 16 + (lane & 15)) * 128 + ks * 32 + cOff;
                ldsm4(bH[fg], sKH + SW128(bb));
                ldsm4(bL[fg], sKL + SW128(bb));
            }
#pragma unroll
            for (int fg = 0; fg < 2; fg++) {
                mma_bf16(qk[2*fg],   aQH[ks], bH[fg][0], bH[fg][2]);
                mma_bf16(qk[2*fg],   aQH[ks], bL[fg][0], bL[fg][2]);
                mma_bf16(qk[2*fg],   aQL,     bH[fg][0], bH[fg][2]);
                mma_bf16(qk[2*fg+1], aQH[ks], bH[fg][1], bH[fg][3]);
                mma_bf16(qk[2*fg+1], aQH[ks], bL[fg][1], bL[fg][3]);
                mma_bf16(qk[2*fg+1], aQL,     bH[fg][1], bH[fg][3]);
            }
        }
        if (j < 63) {
            const int m1 = (j + 1) * 64;
            CP_ASYNC16(sb + FB_KV(b ^ 1) + kvsw,         Khb + (size_t)(m1 + kvr) * HD + kvc * 8);
            CP_ASYNC16(sb + FB_KV(b ^ 1) + 8192 + kvsw,  Klb + (size_t)(m1 + kvr) * HD + kvc * 8);
            CP_ASYNC16(sb + FB_KV(b ^ 1) + 16384 + kvsw, Vhb + (size_t)kvr * NN + m1 + kvc * 8);
            CP_ASYNC16(sb + FB_KV(b ^ 1) + 24576 + kvsw, Vlb + (size_t)kvr * NN + m1 + kvc * 8);
#pragma unroll
            for (int i = 0; i < 4; i++) {
                int idx = t + 512 * i;
                int row = idx >> 4, c4 = idx & 15;
                CP_ASYNC16(sb + FB_ADJ(b ^ 1) + (uint32_t)(row * 272 + c4 * 16),
                           adj + (size_t)(n0 + row) * NN + m1 + c4 * 4);
            }
            CP_COMMIT();
        }
        __syncthreads();   // SYNC1

        // ---- phase B: exp -> P regs; P@V mma; re-init E(b^1) ----
        uint32_t pH0[4], pH8[4], pL0[4], pL8[4];
#pragma unroll
        for (int fi = 0; fi < 4; fi++) {
            int col = wc * 32 + fi * 8 + tg * 2;
            float2 a0 = *(const float2*)(At + rl * 68 + col);
            float2 a8 = *(const float2*)(At + (rl + 8) * 68 + col);
            float2 e0 = *(const float2*)(Et + rl * 66 + col);
            float2 e8 = *(const float2*)(Et + (rl + 8) * 66 + col);
            float p0 = ex2(fmaf(C10, a0.x, qk[fi][0] + e0.x));
            float p1 = ex2(fmaf(C10, a0.y, qk[fi][1] + e0.y));
            float p2 = ex2(fmaf(C10, a8.x, qk[fi][2] + e8.x));
            float p3 = ex2(fmaf(C10, a8.y, qk[fi][3] + e8.y));
            rowsum0 += p0 + p1;
            rowsum8 += p2 + p3;
            uint32_t h0 = cvt2(p0, p1);
            uint32_t h8 = cvt2(p2, p3);
            pH0[fi] = h0; pH8[fi] = h8;
            pL0[fi] = cvt2(p0 - __uint_as_float(h0 << 16),
                           p1 - __uint_as_float(h0 & 0xffff0000u));
            pL8[fi] = cvt2(p2 - __uint_as_float(h8 << 16),
                           p3 - __uint_as_float(h8 & 0xffff0000u));
        }
#pragma unroll
        for (int ks2 = 0; ks2 < 2; ks2++) {
            uint32_t aH[4] = {pH0[2*ks2], pH8[2*ks2], pH0[2*ks2+1], pH8[2*ks2+1]};
            uint32_t aL[4] = {pL0[2*ks2], pL8[2*ks2], pL0[2*ks2+1], pL8[2*ks2+1]};
#pragma unroll
            for (int fg = 0; fg < 4; fg++) {
                uint32_t bb = (fg * 16 + (lane & 15)) * 128 + wc * 64 + ks2 * 32 + cOff;
                uint32_t bH[4], bL[4];
                ldsm4(bH, sVH + SW128(bb));
                ldsm4(bL, sVL + SW128(bb));
                mma_bf16(oacc[2*fg],   aH, bH[0], bH[2]);
                mma_bf16(oacc[2*fg],   aH, bL[0], bL[2]);
                mma_bf16(oacc[2*fg],   aL, bH[0], bH[2]);
                mma_bf16(oacc[2*fg+1], aH, bH[1], bH[3]);
                mma_bf16(oacc[2*fg+1], aH, bL[1], bL[3]);
                mma_bf16(oacc[2*fg+1], aL, bH[1], bH[3]);
            }
        }
        if (j < 63) {
            const uint32_t cbb = __float_as_uint(CB);
            uint4 z = make_uint4(cbb, cbb, cbb, cbb);
            uint4* En = (uint4*)(smem + FB_E(b ^ 1));
            for (int i = t; i < 2112; i += 512) En[i] = z;
        }
        CP_WAIT0();
        __syncthreads();   // SYNC2
    }

    // ---- epilogue ----
    rowsum0 += __shfl_xor_sync(0xffffffffu, rowsum0, 1);
    rowsum0 += __shfl_xor_sync(0xffffffffu, rowsum0, 2);
    rowsum8 += __shfl_xor_sync(0xffffffffu, rowsum8, 1);
    rowsum8 += __shfl_xor_sync(0xffffffffu, rowsum8, 2);
    float* sums = (float*)(smem + FB_SUM);
    if (tg == 0) {
        sums[wc * 128 + rl] = rowsum0;
        sums[wc * 128 + rl + 8] = rowsum8;
    }
    float* buf = (float*)(smem + FB_ADJ(0));
    __syncthreads();
    if (wc == 1) {
#pragma unroll
        for (int fd = 0; fd < 8; fd++) {
            int col = (fd >> 1) * 16 + (fd & 1) * 8 + tg * 2;
            buf[rl * 68 + col]           = oacc[fd][0];
            buf[rl * 68 + col + 1]       = oacc[fd][1];
            buf[(rl + 8) * 68 + col]     = oacc[fd][2];
            buf[(rl + 8) * 68 + col + 1] = oacc[fd][3];
        }
    }
    __syncthreads();
    if (wc == 0) {
        const float ri0 = 1.f / (sums[rl] + sums[128 + rl]);
        const float ri8 = 1.f / (sums[rl + 8] + sums[128 + rl + 8]);
        float* dst0 = g_O + (size_t)(n0 + rl) * DIM + h * HD;
        float* dst8 = g_O + (size_t)(n0 + rl + 8) * DIM + h * HD;
#pragma unroll
        for (int fd = 0; fd < 8; fd++) {
            int col = (fd >> 1) * 16 + (fd & 1) * 8 + tg * 2;
            float2 o0 = { (oacc[fd][0] + buf[rl * 68 + col]) * ri0,
                          (oacc[fd][1] + buf[rl * 68 + col + 1]) * ri0 };
            float2 o1 = { (oacc[fd][2] + buf[(rl + 8) * 68 + col]) * ri8,
                          (oacc[fd][3] + buf[(rl + 8) * 68 + col + 1]) * ri8 };
            *(float2*)(dst0 + col) = o0;
            *(float2*)(dst8 + col) = o1;
        }
    }
}

// =====================================================================
// K4: g_X2 = g_O @ Wo + bo + X
// =====================================================================
__global__ void k_oproj(const float* __restrict__ Wo, const float* __restrict__ bo,
                        const float* __restrict__ X) {
    __shared__ __align__(16) float As[16 * 68];
    __shared__ __align__(16) float Bs[16 * 68];
    const int t  = threadIdx.x;
    const int tx = t & 15, ty = t >> 4;
    const int c0 = blockIdx.x * 64;
    const int r0 = blockIdx.y * 64;

    float acc[16];
#pragma unroll
    for (int i = 0; i < 16; i++) acc[i] = 0.f;

    for (int kc = 0; kc < DIM; kc += 16) {
#pragma unroll
        for (int i = 0; i < 4; i++) {
            int idx = t + 256 * i;
            int r = idx >> 4, kk = idx & 15;
            As[kk * 68 + r] = g_O[(size_t)(r0 + r) * DIM + kc + kk];
        }
#pragma unroll
        for (int i = 0; i < 4; i++) {
            int idx = t + 256 * i;
            int kk = idx >> 6, c = idx & 63;
            Bs[kk * 68 + c] = Wo[(size_t)(kc + kk) * DIM + c0 + c];
        }
        __syncthreads();
#pragma unroll
        for (int kk = 0; kk < 16; kk++) {
            float4 a  = *reinterpret_cast<const float4*>(&As[kk * 68 + ty * 4]);
            float4 bb = *reinterpret_cast<const float4*>(&Bs[kk * 68 + tx * 4]);
            float av[4] = {a.x, a.y, a.z, a.w};
            float bv2[4] = {bb.x, bb.y, bb.z, bb.w};
#pragma unroll
            for (int i = 0; i < 4; i++)
#pragma unroll
                for (int j = 0; j < 4; j++)
                    acc[i * 4 + j] += av[i] * bv2[j];
        }
        __syncthreads();
    }

#pragma unroll
    for (int i = 0; i < 4; i++) {
        int r = r0 + ty * 4 + i;
#pragma unroll
        for (int j = 0; j < 4; j++) {
            int c = c0 + tx * 4 + j;
            g_X2[(size_t)r * DIM + c] = acc[i * 4 + j] + bo[c] + X[(size_t)r * DIM + c];
        }
    }
}

// =====================================================================
// K5: LayerNorm
// =====================================================================
__device__ __forceinline__ float blk_red(float v, float* red) {
    const int lane = threadIdx.x & 31, wid = threadIdx.x >> 5;
#pragma unroll
    for (int o = 16; o; o >>= 1) v += __shfl_xor_sync(0xffffffffu, v, o);
    if (lane == 0) red[wid] = v;
    __syncthreads();
    if (wid == 0) {
        float s = (lane < 8) ? red[lane] : 0.f;
#pragma unroll
        for (int o = 4; o; o >>= 1) s += __shfl_xor_sync(0xffffffffu, s, o);
        if (lane == 0) red[0] = s;
    }
    __syncthreads();
    float r = red[0];
    __syncthreads();
    return r;
}

__global__ void k_ln(const float* __restrict__ gamma, const float* __restrict__ beta,
                     float* __restrict__ out) {
    __shared__ float red[8];
    const int t = threadIdx.x;
    const int n = blockIdx.x;
    float x = g_X2[(size_t)n * DIM + t];
    float mu = blk_red(x, red) * (1.f / DIM);
    float d = x - mu;
    float var = blk_red(d * d, red) * (1.f / DIM);
    out[(size_t)n * DIM + t] = gamma[t] * d * rsqrtf(var + LN_EPS) + beta[t];
}

// =====================================================================
extern "C" void kernel_launch(void* const* d_in, const int* in_sizes, int n_in,
                              void* d_out, int out_size) {
    const float* X    = (const float*)d_in[0];
    const float* adj  = (const float*)d_in[1];
    const float* EF   = (const float*)d_in[2];
    const int*   EI   = (const int*)  d_in[3];
    const float* Wq   = (const float*)d_in[4];
    const float* bq   = (const float*)d_in[5];
    const float* Wk   = (const float*)d_in[6];
    const float* bk   = (const float*)d_in[7];
    const float* Wv   = (const float*)d_in[8];
    const float* bv   = (const float*)d_in[9];
    const float* We   = (const float*)d_in[10];
    const float* be   = (const float*)d_in[11];
    const float* Wo   = (const float*)d_in[12];
    const float* bo   = (const float*)d_in[13];
    const float* gam  = (const float*)d_in[14];
    const float* bet  = (const float*)d_in[15];
    float* out = (float*)d_out;

    cudaFuncSetAttribute(k_fused, cudaFuncAttributeMaxDynamicSharedMemorySize, FS_SMEM);

    k_proj   <<<dim3(4, 64, 3), 256>>>(X, Wq, bq, Wk, bk, Wv, bv);
    k_ea     <<<NE / 64, 256>>>(EF, EI, We, be);
    k_pad    <<<1, 32>>>();
    k_fused  <<<dim3(NH, 32), 512, FS_SMEM>>>(adj, EI);
    k_oproj  <<<dim3(4, 64), 256>>>(Wo, bo, X);
    k_ln     <<<NN, 256>>>(gam, bet, out);
}

// round 9
// speedup vs baseline: 2.7939x; 1.0880x over previous
#include <cuda_runtime.h>
#include <cuda_bf16.h>
#include <cstdint>

#define NN   4096
#define DIM  256
#define NH   4
#define HD   64
#define NE   131072
#define EDIM 64
#define LN_EPS 1e-5f
#define BCAP 128

#define QSC  0.18033688011112042f     // 0.125 * log2(e)
#define C10  14.426950408889634f      // 10 * log2(e)
#define CB  -23.083120654223414f      // -16 * log2(e)

// ---------------- device scratch ----------------
__device__ __nv_bfloat16 g_Qh[NH * NN * HD], g_Ql[NH * NN * HD];  // [h][n][d] (scaled)
__device__ __nv_bfloat16 g_Kh[NH * NN * HD], g_Kl[NH * NN * HD];  // [h][m][d]
__device__ __nv_bfloat16 g_Vh[NH * HD * NN], g_Vl[NH * HD * NN];  // [h][d][m]
__device__ float g_EA[(size_t)NE * NH];       // edge bias * 0.1 (folds /10 for C10 merge)
__device__ int   g_bcnt[4096];
__device__ int   g_blist[4096 * BCAP];
__device__ int   g_pad;
__device__ float g_O[NN * DIM];
__device__ float g_X2[NN * DIM];

// ---------------- helpers ----------------
__device__ __forceinline__ uint32_t smem_to_u32(const void* p) {
    uint32_t a;
    asm("{ .reg .u64 t; cvta.to.shared.u64 t, %1; cvt.u32.u64 %0, t; }" : "=r"(a) : "l"(p));
    return a;
}
#define SW128(b) ((b) ^ (((b) >> 3) & 0x70))
#define CP_ASYNC16(dst, src) \
    asm volatile("cp.async.cg.shared.global [%0], [%1], 16;" :: "r"(dst), "l"(src))
#define CP_COMMIT() asm volatile("cp.async.commit_group;" ::: "memory")
#define CP_WAIT0()  asm volatile("cp.async.wait_group 0;" ::: "memory")

__device__ __forceinline__ void ldsm4(uint32_t r[4], uint32_t addr) {
    asm volatile("ldmatrix.sync.aligned.m8n8.x4.shared.b16 {%0,%1,%2,%3}, [%4];"
        : "=r"(r[0]), "=r"(r[1]), "=r"(r[2]), "=r"(r[3]) : "r"(addr));
}
__device__ __forceinline__ void mma_bf16(float c[4], const uint32_t a[4],
                                         uint32_t b0, uint32_t b1) {
    asm volatile("mma.sync.aligned.m16n8k16.row.col.f32.bf16.bf16.f32 "
        "{%0,%1,%2,%3}, {%4,%5,%6,%7}, {%8,%9}, {%0,%1,%2,%3};"
        : "+f"(c[0]), "+f"(c[1]), "+f"(c[2]), "+f"(c[3])
        : "r"(a[0]), "r"(a[1]), "r"(a[2]), "r"(a[3]), "r"(b0), "r"(b1));
}
__device__ __forceinline__ float ex2(float x) {
    float r;
    asm("ex2.approx.f32 %0, %1;" : "=f"(r) : "f"(x));
    return r;
}
__device__ __forceinline__ uint32_t cvt2(float lo, float hi) {   // pack {lo, hi}
    uint32_t r;
    asm("cvt.rn.bf16x2.f32 %0, %1, %2;" : "=r"(r) : "f"(hi), "f"(lo));
    return r;
}

// =====================================================================
// K1: fused QKV projection -> bf16 hi/lo splits (Q pre-scaled). Zeros g_bcnt.
// =====================================================================
__global__ void k_proj(const float* __restrict__ X,
                       const float* __restrict__ Wq, const float* __restrict__ bq,
                       const float* __restrict__ Wk, const float* __restrict__ bk,
                       const float* __restrict__ Wv, const float* __restrict__ bv) {
    __shared__ __align__(16) float As[16 * 68];
    __shared__ __align__(16) float Bs[16 * 68];
    const int t  = threadIdx.x;
    const int tx = t & 15, ty = t >> 4;
    const int c0 = blockIdx.x * 64;
    const int r0 = blockIdx.y * 64;
    const int z  = blockIdx.z;
    if (z == 0 && blockIdx.x == 0 && blockIdx.y < 16)
        g_bcnt[blockIdx.y * 256 + t] = 0;
    const float* W = (z == 0) ? Wq : (z == 1) ? Wk : Wv;
    const float* b = (z == 0) ? bq : (z == 1) ? bk : bv;

    float acc[16];
#pragma unroll
    for (int i = 0; i < 16; i++) acc[i] = 0.f;

    for (int kc = 0; kc < DIM; kc += 16) {
#pragma unroll
        for (int i = 0; i < 4; i++) {
            int idx = t + 256 * i;
            int r = idx >> 4, kk = idx & 15;
            As[kk * 68 + r] = X[(size_t)(r0 + r) * DIM + kc + kk];
        }
#pragma unroll
        for (int i = 0; i < 4; i++) {
            int idx = t + 256 * i;
            int kk = idx >> 6, c = idx & 63;
            Bs[kk * 68 + c] = W[(size_t)(kc + kk) * DIM + c0 + c];
        }
        __syncthreads();
#pragma unroll
        for (int kk = 0; kk < 16; kk++) {
            float4 a  = *reinterpret_cast<const float4*>(&As[kk * 68 + ty * 4]);
            float4 bb = *reinterpret_cast<const float4*>(&Bs[kk * 68 + tx * 4]);
            float av[4] = {a.x, a.y, a.z, a.w};
            float bv2[4] = {bb.x, bb.y, bb.z, bb.w};
#pragma unroll
            for (int i = 0; i < 4; i++)
#pragma unroll
                for (int j = 0; j < 4; j++)
                    acc[i * 4 + j] += av[i] * bv2[j];
        }
        __syncthreads();
    }

#pragma unroll
    for (int i = 0; i < 4; i++) {
        int r = r0 + ty * 4 + i;
#pragma unroll
        for (int j = 0; j < 4; j++) {
            int c = c0 + tx * 4 + j;
            float v = acc[i * 4 + j] + b[c];
            if (z == 0) v *= QSC;
            int h = c >> 6, d = c & 63;
            __nv_bfloat16 hi = __float2bfloat16(v);
            __nv_bfloat16 lo = __float2bfloat16(v - __bfloat162float(hi));
            if (z == 0) {
                size_t idx = ((size_t)h * NN + r) * HD + d;
                g_Qh[idx] = hi; g_Ql[idx] = lo;
            } else if (z == 1) {
                size_t idx = ((size_t)h * NN + r) * HD + d;
                g_Kh[idx] = hi; g_Kl[idx] = lo;
            } else {
                size_t idx = ((size_t)h * HD + d) * NN + r;
                g_Vh[idx] = hi; g_Vl[idx] = lo;
            }
        }
    }
}

// =====================================================================
// K2: per-edge bias GEMM -> g_EA (x 0.1); direct bucket scatter (64x64 keys).
// =====================================================================
__global__ void k_ea(const float* __restrict__ EF, const int* __restrict__ EI,
                     const float* __restrict__ We, const float* __restrict__ be) {
    __shared__ float ef[64][65];
    __shared__ float w[EDIM][NH];
    __shared__ float bsh[NH];
    const int t  = threadIdx.x;
    const int e0 = blockIdx.x * 64;
#pragma unroll
    for (int i = 0; i < 16; i++) {
        int idx = t + 256 * i;
        ef[idx >> 6][idx & 63] = EF[(size_t)e0 * EDIM + idx];
    }
    if (t < EDIM * NH) w[t >> 2][t & 3] = We[t];
    if (t < NH) bsh[t] = be[t];
    __syncthreads();

    const int el = t >> 2, h = t & 3;
    const int e = e0 + el;
    float s = bsh[h];
#pragma unroll
    for (int k = 0; k < EDIM; k++) s += ef[el][k] * w[k][h];
    g_EA[(size_t)e * NH + h] = s * 0.1f;          // /10: folded back via C10 later
    if (h == 0) {
        int key = (EI[2 * e] >> 6) * 64 + ((EI[2 * e + 1] >> 6) & 63);
        int pos = atomicAdd(&g_bcnt[key], 1);
        if (pos < BCAP) g_blist[key * BCAP + pos] = e;
    }
}

// padding kernel so k_fused is the 4th launch (ncu captures launch #4)
__global__ void k_pad() { if (threadIdx.x == 0) g_pad = 1; }

// =====================================================================
// K3: FUSED attention v5. 256 threads / 8 warps, 2 CTAs/SM.
// CTA = (head, 64-row nb). Warp grid 4n x 2m; warp tile 16n x 32m.
// Edge biases atomicAdd'ed into the adj SMEM tile (no E tile).
// CB folded into qk accumulator init.
// smem: QL 8K @0 | ADJ(b) @8192+b*17408 (64x68 f32) | KV(b) @43008+b*32768 |
//       sums @108544 (128 f32) ; total 109056
// =====================================================================
#define FB_QL     0u
#define FB_ADJ(b) (8192u + (b) * 17408u)
#define FB_KV(b)  (43008u + (b) * 32768u)
#define FB_SUM    108544u
#define FS_SMEM   109056

__global__ void __launch_bounds__(256, 2) k_fused(const float* __restrict__ adj,
                                                  const int* __restrict__ EI) {
    extern __shared__ char smem[];
    const uint32_t sb = smem_to_u32(smem);
    const int t = threadIdx.x, lane = t & 31, w = t >> 5;
    const int wr = w & 3, wc = w >> 2;
    const int h = blockIdx.x, nb = blockIdx.y, n0 = nb * 64;

    const int g  = lane >> 2, tg = lane & 3;
    const int rl = wr * 16 + g;
    const uint32_t aRow = wr * 16 + (lane & 15);
    const uint32_t cOff = (lane >> 4) * 16;

    const __nv_bfloat16* Khb = g_Kh + (size_t)h * NN * HD;
    const __nv_bfloat16* Klb = g_Kl + (size_t)h * NN * HD;
    const __nv_bfloat16* Vhb = g_Vh + (size_t)h * HD * NN;
    const __nv_bfloat16* Vlb = g_Vl + (size_t)h * HD * NN;

    // ---------- prologue ----------
    const int kvc = t & 7;
#pragma unroll
    for (int i = 0; i < 2; i++) {
        int r = (t >> 3) + 32 * i;
        uint32_t sw = SW128((uint32_t)(r * 128 + kvc * 16));
        CP_ASYNC16(sb + FB_KV(0) + sw,          Khb + (size_t)r * HD + kvc * 8);
        CP_ASYNC16(sb + FB_KV(0) + 8192 + sw,   Klb + (size_t)r * HD + kvc * 8);
        CP_ASYNC16(sb + FB_KV(0) + 16384 + sw,  Vhb + (size_t)r * NN + kvc * 8);
        CP_ASYNC16(sb + FB_KV(0) + 24576 + sw,  Vlb + (size_t)r * NN + kvc * 8);
    }
    CP_COMMIT();
    // QL -> resident @0 ; QH staged into ADJ(0) area
    {
        const uint4* qh = (const uint4*)(g_Qh + ((size_t)h * NN + n0) * HD);
        const uint4* ql = (const uint4*)(g_Ql + ((size_t)h * NN + n0) * HD);
#pragma unroll
        for (int i = 0; i < 2; i++) {
            int e = t + 256 * i;
            uint32_t sw = SW128((uint32_t)e * 16);
            *(uint4*)(smem + FB_QL + sw)      = ql[e];
            *(uint4*)(smem + FB_ADJ(0) + sw)  = qh[e];
        }
    }
    __syncthreads();

    uint32_t aQH[4][4];
#pragma unroll
    for (int ks = 0; ks < 4; ks++) {
        uint32_t byte = aRow * 128 + ks * 32 + cOff;
        ldsm4(aQH[ks], sb + FB_ADJ(0) + SW128(byte));
    }
    __syncthreads();   // QH stage region free -> ADJ(0)

#pragma unroll
    for (int i = 0; i < 4; i++) {
        int idx = t + 256 * i;
        int row = idx >> 4, c4 = idx & 15;
        CP_ASYNC16(sb + FB_ADJ(0) + (uint32_t)(row * 272 + c4 * 16),
                   adj + (size_t)(n0 + row) * NN + c4 * 4);
    }
    CP_COMMIT();
    CP_WAIT0();
    __syncthreads();

    float oacc[8][4];
#pragma unroll
    for (int fd = 0; fd < 8; fd++)
#pragma unroll
        for (int k = 0; k < 4; k++) oacc[fd][k] = 0.f;
    float rowsum0 = 0.f, rowsum8 = 0.f;

    for (int j = 0; j < 64; j++) {
        const int b = j & 1;
        const uint32_t sKH = sb + FB_KV(b), sKL = sKH + 8192;
        const uint32_t sVH = sKH + 16384,  sVL = sKH + 24576;
        float* At = (float*)(smem + FB_ADJ(b));

        // ---- phase A: edge scatter into At(b); QK mma; cp.async next ----
        {
            int key = nb * 64 + j;
            int cnt = g_bcnt[key];
            int base = key * BCAP;
            for (int i = t; i < cnt; i += 256) {
                int e = g_blist[base + i];
                atomicAdd(&At[(EI[2 * e] & 63) * 68 + (EI[2 * e + 1] & 63)],
                          g_EA[(size_t)e * NH + h]);
            }
        }
        float qk[4][4];
#pragma unroll
        for (int fi = 0; fi < 4; fi++)
#pragma unroll
            for (int k = 0; k < 4; k++) qk[fi][k] = CB;   // fold -16*log2e here
#pragma unroll
        for (int ks = 0; ks < 4; ks++) {
            uint32_t byte = aRow * 128 + ks * 32 + cOff;
            uint32_t aQL[4];
            ldsm4(aQL, sb + FB_QL + SW128(byte));
            uint32_t bH[2][4], bL[2][4];
#pragma unroll
            for (int fg = 0; fg < 2; fg++) {
                uint32_t bb = (wc * 32 + fg * 16 + (lane & 15)) * 128 + ks * 32 + cOff;
                ldsm4(bH[fg], sKH + SW128(bb));
                ldsm4(bL[fg], sKL + SW128(bb));
            }
#pragma unroll
            for (int fg = 0; fg < 2; fg++) {
                mma_bf16(qk[2*fg],   aQH[ks], bH[fg][0], bH[fg][2]);
                mma_bf16(qk[2*fg],   aQH[ks], bL[fg][0], bL[fg][2]);
                mma_bf16(qk[2*fg],   aQL,     bH[fg][0], bH[fg][2]);
                mma_bf16(qk[2*fg+1], aQH[ks], bH[fg][1], bH[fg][3]);
                mma_bf16(qk[2*fg+1], aQH[ks], bL[fg][1], bL[fg][3]);
                mma_bf16(qk[2*fg+1], aQL,     bH[fg][1], bH[fg][3]);
            }
        }
        if (j < 63) {
            const int m1 = (j + 1) * 64;
#pragma unroll
            for (int i = 0; i < 2; i++) {
                int r = (t >> 3) + 32 * i;
                uint32_t sw = SW128((uint32_t)(r * 128 + kvc * 16));
                CP_ASYNC16(sb + FB_KV(b ^ 1) + sw,         Khb + (size_t)(m1 + r) * HD + kvc * 8);
                CP_ASYNC16(sb + FB_KV(b ^ 1) + 8192 + sw,  Klb + (size_t)(m1 + r) * HD + kvc * 8);
                CP_ASYNC16(sb + FB_KV(b ^ 1) + 16384 + sw, Vhb + (size_t)r * NN + m1 + kvc * 8);
                CP_ASYNC16(sb + FB_KV(b ^ 1) + 24576 + sw, Vlb + (size_t)r * NN + m1 + kvc * 8);
            }
#pragma unroll
            for (int i = 0; i < 4; i++) {
                int idx = t + 256 * i;
                int row = idx >> 4, c4 = idx & 15;
                CP_ASYNC16(sb + FB_ADJ(b ^ 1) + (uint32_t)(row * 272 + c4 * 16),
                           adj + (size_t)(n0 + row) * NN + m1 + c4 * 4);
            }
            CP_COMMIT();
        }
        __syncthreads();   // SYNC1

        // ---- phase B: exp -> P regs; P@V mma ----
        uint32_t pH0[4], pH8[4], pL0[4], pL8[4];
#pragma unroll
        for (int fi = 0; fi < 4; fi++) {
            int col = wc * 32 + fi * 8 + tg * 2;
            float2 a0 = *(const float2*)(At + rl * 68 + col);
            float2 a8 = *(const float2*)(At + (rl + 8) * 68 + col);
            float p0 = ex2(fmaf(C10, a0.x, qk[fi][0]));
            float p1 = ex2(fmaf(C10, a0.y, qk[fi][1]));
            float p2 = ex2(fmaf(C10, a8.x, qk[fi][2]));
            float p3 = ex2(fmaf(C10, a8.y, qk[fi][3]));
            rowsum0 += p0 + p1;
            rowsum8 += p2 + p3;
            uint32_t h0 = cvt2(p0, p1);
            uint32_t h8 = cvt2(p2, p3);
            pH0[fi] = h0; pH8[fi] = h8;
            pL0[fi] = cvt2(p0 - __uint_as_float(h0 << 16),
                           p1 - __uint_as_float(h0 & 0xffff0000u));
            pL8[fi] = cvt2(p2 - __uint_as_float(h8 << 16),
                           p3 - __uint_as_float(h8 & 0xffff0000u));
        }
#pragma unroll
        for (int ks2 = 0; ks2 < 2; ks2++) {
            uint32_t aH[4] = {pH0[2*ks2], pH8[2*ks2], pH0[2*ks2+1], pH8[2*ks2+1]};
            uint32_t aL[4] = {pL0[2*ks2], pL8[2*ks2], pL0[2*ks2+1], pL8[2*ks2+1]};
#pragma unroll
            for (int fg = 0; fg < 4; fg++) {
                uint32_t bb = (fg * 16 + (lane & 15)) * 128 + wc * 64 + ks2 * 32 + cOff;
                uint32_t bH[4], bL[4];
                ldsm4(bH, sVH + SW128(bb));
                ldsm4(bL, sVL + SW128(bb));
                mma_bf16(oacc[2*fg],   aH, bH[0], bH[2]);
                mma_bf16(oacc[2*fg],   aH, bL[0], bL[2]);
                mma_bf16(oacc[2*fg],   aL, bH[0], bH[2]);
                mma_bf16(oacc[2*fg+1], aH, bH[1], bH[3]);
                mma_bf16(oacc[2*fg+1], aH, bL[1], bL[3]);
                mma_bf16(oacc[2*fg+1], aL, bH[1], bH[3]);
            }
        }
        CP_WAIT0();
        __syncthreads();   // SYNC2
    }

    // ---- epilogue ----
    rowsum0 += __shfl_xor_sync(0xffffffffu, rowsum0, 1);
    rowsum0 += __shfl_xor_sync(0xffffffffu, rowsum0, 2);
    rowsum8 += __shfl_xor_sync(0xffffffffu, rowsum8, 1);
    rowsum8 += __shfl_xor_sync(0xffffffffu, rowsum8, 2);
    float* sums = (float*)(smem + FB_SUM);
    if (tg == 0) {
        sums[wc * 64 + rl] = rowsum0;
        sums[wc * 64 + rl + 8] = rowsum8;
    }
    float* buf = (float*)(smem + FB_ADJ(0));
    __syncthreads();
    if (wc == 1) {
#pragma unroll
        for (int fd = 0; fd < 8; fd++) {
            int col = (fd >> 1) * 16 + (fd & 1) * 8 + tg * 2;
            buf[rl * 68 + col]           = oacc[fd][0];
            buf[rl * 68 + col + 1]       = oacc[fd][1];
            buf[(rl + 8) * 68 + col]     = oacc[fd][2];
            buf[(rl + 8) * 68 + col + 1] = oacc[fd][3];
        }
    }
    __syncthreads();
    if (wc == 0) {
        const float ri0 = 1.f / (sums[rl] + sums[64 + rl]);
        const float ri8 = 1.f / (sums[rl + 8] + sums[64 + rl + 8]);
        float* dst0 = g_O + (size_t)(n0 + rl) * DIM + h * HD;
        float* dst8 = g_O + (size_t)(n0 + rl + 8) * DIM + h * HD;
#pragma unroll
        for (int fd = 0; fd < 8; fd++) {
            int col = (fd >> 1) * 16 + (fd & 1) * 8 + tg * 2;
            float2 o0 = { (oacc[fd][0] + buf[rl * 68 + col]) * ri0,
                          (oacc[fd][1] + buf[rl * 68 + col + 1]) * ri0 };
            float2 o1 = { (oacc[fd][2] + buf[(rl + 8) * 68 + col]) * ri8,
                          (oacc[fd][3] + buf[(rl + 8) * 68 + col + 1]) * ri8 };
            *(float2*)(dst0 + col) = o0;
            *(float2*)(dst8 + col) = o1;
        }
    }
}

// =====================================================================
// K4: g_X2 = g_O @ Wo + bo + X
// =====================================================================
__global__ void k_oproj(const float* __restrict__ Wo, const float* __restrict__ bo,
                        const float* __restrict__ X) {
    __shared__ __align__(16) float As[16 * 68];
    __shared__ __align__(16) float Bs[16 * 68];
    const int t  = threadIdx.x;
    const int tx = t & 15, ty = t >> 4;
    const int c0 = blockIdx.x * 64;
    const int r0 = blockIdx.y * 64;

    float acc[16];
#pragma unroll
    for (int i = 0; i < 16; i++) acc[i] = 0.f;

    for (int kc = 0; kc < DIM; kc += 16) {
#pragma unroll
        for (int i = 0; i < 4; i++) {
            int idx = t + 256 * i;
            int r = idx >> 4, kk = idx & 15;
            As[kk * 68 + r] = g_O[(size_t)(r0 + r) * DIM + kc + kk];
        }
#pragma unroll
        for (int i = 0; i < 4; i++) {
            int idx = t + 256 * i;
            int kk = idx >> 6, c = idx & 63;
            Bs[kk * 68 + c] = Wo[(size_t)(kc + kk) * DIM + c0 + c];
        }
        __syncthreads();
#pragma unroll
        for (int kk = 0; kk < 16; kk++) {
            float4 a  = *reinterpret_cast<const float4*>(&As[kk * 68 + ty * 4]);
            float4 bb = *reinterpret_cast<const float4*>(&Bs[kk * 68 + tx * 4]);
            float av[4] = {a.x, a.y, a.z, a.w};
            float bv2[4] = {bb.x, bb.y, bb.z, bb.w};
#pragma unroll
            for (int i = 0; i < 4; i++)
#pragma unroll
                for (int j = 0; j < 4; j++)
                    acc[i * 4 + j] += av[i] * bv2[j];
        }
        __syncthreads();
    }

#pragma unroll
    for (int i = 0; i < 4; i++) {
        int r = r0 + ty * 4 + i;
#pragma unroll
        for (int j = 0; j < 4; j++) {
            int c = c0 + tx * 4 + j;
            g_X2[(size_t)r * DIM + c] = acc[i * 4 + j] + bo[c] + X[(size_t)r * DIM + c];
        }
    }
}

// =====================================================================
// K5: LayerNorm
// =====================================================================
__device__ __forceinline__ float blk_red(float v, float* red) {
    const int lane = threadIdx.x & 31, wid = threadIdx.x >> 5;
#pragma unroll
    for (int o = 16; o; o >>= 1) v += __shfl_xor_sync(0xffffffffu, v, o);
    if (lane == 0) red[wid] = v;
    __syncthreads();
    if (wid == 0) {
        float s = (lane < 8) ? red[lane] : 0.f;
#pragma unroll
        for (int o = 4; o; o >>= 1) s += __shfl_xor_sync(0xffffffffu, s, o);
        if (lane == 0) red[0] = s;
    }
    __syncthreads();
    float r = red[0];
    __syncthreads();
    return r;
}

__global__ void k_ln(const float* __restrict__ gamma, const float* __restrict__ beta,
                     float* __restrict__ out) {
    __shared__ float red[8];
    const int t = threadIdx.x;
    const int n = blockIdx.x;
    float x = g_X2[(size_t)n * DIM + t];
    float mu = blk_red(x, red) * (1.f / DIM);
    float d = x - mu;
    float var = blk_red(d * d, red) * (1.f / DIM);
    out[(size_t)n * DIM + t] = gamma[t] * d * rsqrtf(var + LN_EPS) + beta[t];
}

// =====================================================================
extern "C" void kernel_launch(void* const* d_in, const int* in_sizes, int n_in,
                              void* d_out, int out_size) {
    const float* X    = (const float*)d_in[0];
    const float* adj  = (const float*)d_in[1];
    const float* EF   = (const float*)d_in[2];
    const int*   EI   = (const int*)  d_in[3];
    const float* Wq   = (const float*)d_in[4];
    const float* bq   = (const float*)d_in[5];
    const float* Wk   = (const float*)d_in[6];
    const float* bk   = (const float*)d_in[7];
    const float* Wv   = (const float*)d_in[8];
    const float* bv   = (const float*)d_in[9];
    const float* We   = (const float*)d_in[10];
    const float* be   = (const float*)d_in[11];
    const float* Wo   = (const float*)d_in[12];
    const float* bo   = (const float*)d_in[13];
    const float* gam  = (const float*)d_in[14];
    const float* bet  = (const float*)d_in[15];
    float* out = (float*)d_out;

    cudaFuncSetAttribute(k_fused, cudaFuncAttributeMaxDynamicSharedMemorySize, FS_SMEM);

    k_proj   <<<dim3(4, 64, 3), 256>>>(X, Wq, bq, Wk, bk, Wv, bv);
    k_ea     <<<NE / 64, 256>>>(EF, EI, We, be);
    k_pad    <<<1, 32>>>();
    k_fused  <<<dim3(NH, 64), 256, FS_SMEM>>>(adj, EI);
    k_oproj  <<<dim3(4, 64), 256>>>(Wo, bo, X);
    k_ln     <<<NN, 256>>>(gam, bet, out);
}